// round 1
// baseline (speedup 1.0000x reference)
#include <cuda_runtime.h>
#include <math.h>

#define MEMN 32768
#define BATCH 256
#define UNITS 128
#define IN_DIM 512

#define OFF_READ    0
#define OFF_MEMORY  (OFF_READ + BATCH*UNITS)
#define OFF_CWU     (OFF_MEMORY + MEMN*UNITS)
#define OFF_CWLU    (OFF_CWU + MEMN*BATCH)
#define OFF_CWR     (OFF_CWLU + MEMN*BATCH)
#define OFF_CWW     (OFF_CWR + MEMN*BATCH)
#define OFF_H       (OFF_CWW + MEMN*BATCH)
#define OFF_C       (OFF_H + BATCH*UNITS)

// scratch (device globals: no allocation allowed)
__device__ float g_h[BATCH*UNITS];
__device__ float g_hT[UNITS*BATCH];          // [k][b]
__device__ float g_kinv[BATCH];
__device__ float g_minv[MEMN];
__device__ float g_cos[MEMN*BATCH];          // 32 MB scratch
__device__ unsigned long long g_part[256*256];
__device__ float g_colmin[BATCH];
__device__ int   g_cnt[MEMN];

__device__ __forceinline__ unsigned ordf(float f) {
    unsigned u = __float_as_uint(f);
    return (u & 0x80000000u) ? ~u : (u | 0x80000000u);
}

// ---------------- init: zero read output + cnt ----------------
__global__ void k_init(float* __restrict__ out_read) {
    int i = blockIdx.x * 256 + threadIdx.x;
    if (i < MEMN) g_cnt[i] = 0;
    if (i < BATCH*UNITS) out_read[i] = 0.f;
}

// ---------------- LSTM cell ----------------
// z(256x512) = [inputs|r_tm1|h_tm1](256x768) @ [kernel;rec_kernel](768x512) + bias
// tile 16b x 16u, 4 gates per thread. grid (8 utiles, 16 btiles), 256 thr.
__global__ void k_lstm(const float* __restrict__ inputs, const float* __restrict__ r_tm1,
                       const float* __restrict__ h_tm1, const float* __restrict__ c_tm1,
                       const float* __restrict__ Wk, const float* __restrict__ Wr,
                       const float* __restrict__ bias, float* __restrict__ out) {
    __shared__ float sA[16][128];
    __shared__ float sB[128][64];
    int t = threadIdx.x;
    int utile = blockIdx.x, btile = blockIdx.y;
    int ul = t & 15, bl = t >> 4;
    float acc[4] = {0.f, 0.f, 0.f, 0.f};

    for (int kc = 0; kc < 6; kc++) {
        #pragma unroll
        for (int p = 0; p < 2; p++) {
            int i = t + p * 256;
            int row = i >> 5, c4 = (i & 31) * 4;
            int b = btile * 16 + row;
            const float* src;
            if (kc < 4)       src = inputs + b * IN_DIM + kc * 128 + c4;
            else if (kc == 4) src = r_tm1 + b * UNITS + c4;
            else              src = h_tm1 + b * UNITS + c4;
            *(float4*)&sA[row][c4] = *(const float4*)src;
        }
        #pragma unroll
        for (int p = 0; p < 8; p++) {
            int i = t + p * 256;
            int k = i >> 4, c4 = (i & 15) * 4;
            int q = c4 >> 4, jr = c4 & 15;
            int jc = utile * 16 + jr + q * 128;
            float4 v;
            if (kc < 5) v = *(const float4*)(Wk + (kc * 128 + k) * 512 + jc);
            else        v = *(const float4*)(Wr + k * 512 + jc);
            *(float4*)&sB[k][c4] = v;
        }
        __syncthreads();
        #pragma unroll 8
        for (int k = 0; k < 128; k++) {
            float a = sA[bl][k];
            acc[0] += a * sB[k][ul];
            acc[1] += a * sB[k][16 + ul];
            acc[2] += a * sB[k][32 + ul];
            acc[3] += a * sB[k][48 + ul];
        }
        __syncthreads();
    }
    int b = btile * 16 + bl, u = utile * 16 + ul;
    float zi = acc[0] + bias[u];
    float zf = acc[1] + bias[128 + u];
    float zg = acc[2] + bias[256 + u];
    float zo = acc[3] + bias[384 + u];
    float si = 1.f / (1.f + expf(-zi));
    float sf = 1.f / (1.f + expf(-zf));
    float so = 1.f / (1.f + expf(-zo));
    float cn = sf * c_tm1[b * UNITS + u] + si * tanhf(zg);
    float hn = so * tanhf(cn);
    out[OFF_H + b * UNITS + u] = hn;
    out[OFF_C + b * UNITS + u] = cn;
    g_h[b * UNITS + u] = hn;
}

// ---------------- key inverse norms + h transpose ----------------
// grid 32 x 256, warp per batch
__global__ void k_knorm() {
    int t = threadIdx.x, w = t >> 5, l = t & 31;
    int b = blockIdx.x * 8 + w;
    float s = 0.f;
    #pragma unroll
    for (int i = 0; i < 4; i++) { float v = g_h[b * UNITS + l + 32 * i]; s += v * v; }
    #pragma unroll
    for (int o = 16; o; o >>= 1) s += __shfl_xor_sync(0xffffffffu, s, o);
    if (l == 0) g_kinv[b] = rsqrtf(fmaxf(s, 1e-12f));
    #pragma unroll
    for (int p = 0; p < 4; p++) {
        int idx = blockIdx.x * 1024 + p * 256 + t;
        g_hT[(idx & 127) * BATCH + (idx >> 7)] = g_h[idx];
    }
}

// ---------------- memory row inverse norms ---------------- grid 4096 x 256
__global__ void k_minv(const float* __restrict__ m) {
    int t = threadIdx.x, w = t >> 5, l = t & 31;
    int row = blockIdx.x * 8 + w;
    float s = 0.f;
    #pragma unroll
    for (int i = 0; i < 4; i++) { float v = m[row * UNITS + l + 32 * i]; s += v * v; }
    #pragma unroll
    for (int o = 16; o; o >>= 1) s += __shfl_xor_sync(0xffffffffu, s, o);
    if (l == 0) g_minv[row] = rsqrtf(fmaxf(s, 1e-12f));
}

// ---------------- cosine GEMM: cos[m,b] = minv[m]*kinv[b]* (m_row . h_b) ----
// tile 64m x 64b, K=128 in 2 chunks. grid (4 btile, 512 mtile), 256 thr, 4x4 micro.
__global__ void k_cos(const float* __restrict__ m) {
    __shared__ float sA[64][68];
    __shared__ float sB[64][64];
    int t = threadIdx.x;
    int btile = blockIdx.x, mtile = blockIdx.y;
    int bx = t & 15, mg = t >> 4;
    float acc[4][4];
    #pragma unroll
    for (int i = 0; i < 4; i++)
        #pragma unroll
        for (int j = 0; j < 4; j++) acc[i][j] = 0.f;

    for (int kc = 0; kc < 2; kc++) {
        int kb = kc * 64;
        #pragma unroll
        for (int p = 0; p < 4; p++) {
            int i = t + p * 256;
            int r = i >> 4, c4 = (i & 15) * 4;
            *(float4*)&sA[r][c4] = *(const float4*)(m + (mtile * 64 + r) * UNITS + kb + c4);
            *(float4*)&sB[r][c4] = *(const float4*)(g_hT + (kb + r) * BATCH + btile * 64 + c4);
        }
        __syncthreads();
        #pragma unroll 4
        for (int k = 0; k < 64; k++) {
            float a0 = sA[mg * 4 + 0][k];
            float a1 = sA[mg * 4 + 1][k];
            float a2 = sA[mg * 4 + 2][k];
            float a3 = sA[mg * 4 + 3][k];
            float4 bv = *(float4*)&sB[k][bx * 4];
            acc[0][0] += a0 * bv.x; acc[0][1] += a0 * bv.y; acc[0][2] += a0 * bv.z; acc[0][3] += a0 * bv.w;
            acc[1][0] += a1 * bv.x; acc[1][1] += a1 * bv.y; acc[1][2] += a1 * bv.z; acc[1][3] += a1 * bv.w;
            acc[2][0] += a2 * bv.x; acc[2][1] += a2 * bv.y; acc[2][2] += a2 * bv.z; acc[2][3] += a2 * bv.w;
            acc[3][0] += a3 * bv.x; acc[3][1] += a3 * bv.y; acc[3][2] += a3 * bv.z; acc[3][3] += a3 * bv.w;
        }
        __syncthreads();
    }
    float kinv[4];
    #pragma unroll
    for (int j = 0; j < 4; j++) kinv[j] = g_kinv[btile * 64 + bx * 4 + j];
    #pragma unroll
    for (int i = 0; i < 4; i++) {
        int mr = mtile * 64 + mg * 4 + i;
        float mi = g_minv[mr];
        float4 o;
        o.x = acc[i][0] * mi * kinv[0];
        o.y = acc[i][1] * mi * kinv[1];
        o.z = acc[i][2] * mi * kinv[2];
        o.w = acc[i][3] * mi * kinv[3];
        *(float4*)(g_cos + mr * BATCH + btile * 64 + bx * 4) = o;
    }
}

// ---------------- softmax + c_ww + c_wu + per-column min partials ----------
// grid 256 blocks (128 rows each), 8 warps, warp per row iteration.
__global__ void k_soft(const float* __restrict__ wr_tm1, const float* __restrict__ wlu_tm1,
                       const float* __restrict__ wu_tm1, const float* __restrict__ wgate,
                       float* __restrict__ out) {
    __shared__ unsigned long long s_enc[8][256];
    int t = threadIdx.x, w = t >> 5, l = t & 31;
    float wg = 1.f / (1.f + __expf(-wgate[0]));
    float omw = 1.f - wg;
    unsigned long long emin[8];
    #pragma unroll
    for (int j = 0; j < 8; j++) emin[j] = 0xFFFFFFFFFFFFFFFFull;

    for (int i = 0; i < 16; i++) {
        int r = blockIdx.x * 128 + w * 16 + i;
        float x[8];
        #pragma unroll
        for (int j = 0; j < 8; j++) x[j] = g_cos[r * BATCH + l + 32 * j];
        float mx = x[0];
        #pragma unroll
        for (int j = 1; j < 8; j++) mx = fmaxf(mx, x[j]);
        #pragma unroll
        for (int o = 16; o; o >>= 1) mx = fmaxf(mx, __shfl_xor_sync(0xffffffffu, mx, o));
        float e[8], s = 0.f;
        #pragma unroll
        for (int j = 0; j < 8; j++) { e[j] = __expf(x[j] - mx); s += e[j]; }
        #pragma unroll
        for (int o = 16; o; o >>= 1) s += __shfl_xor_sync(0xffffffffu, s, o);
        float inv = 1.f / s;
        #pragma unroll
        for (int j = 0; j < 8; j++) {
            int c = l + 32 * j;
            int idx = r * BATCH + c;
            float wr = e[j] * inv;
            float ww = wg * wr_tm1[idx] + omw + wlu_tm1[idx];
            float wu = 0.95f * wu_tm1[idx] + wr + ww;
            out[OFF_CWR + idx] = wr;
            out[OFF_CWW + idx] = ww;
            out[OFF_CWU + idx] = wu;
            unsigned long long enc = ((unsigned long long)ordf(wu) << 32)
                                   | (unsigned long long)(0xFFFFFFFFu - (unsigned)r);
            emin[j] = (enc < emin[j]) ? enc : emin[j];
        }
    }
    #pragma unroll
    for (int j = 0; j < 8; j++) s_enc[w][l + 32 * j] = emin[j];
    __syncthreads();
    unsigned long long e = s_enc[0][t];
    #pragma unroll
    for (int w2 = 1; w2 < 8; w2++) { unsigned long long v = s_enc[w2][t]; e = (v < e) ? v : e; }
    g_part[blockIdx.x * 256 + t] = e;
}

// ---------------- argmin finalize: column mins + counts ---------------- 1 x 256
__global__ void k_argmin() {
    int c = threadIdx.x;
    unsigned long long e = 0xFFFFFFFFFFFFFFFFull;
    for (int i = 0; i < 256; i++) {
        unsigned long long v = g_part[i * 256 + c];
        e = (v < e) ? v : e;
    }
    unsigned hi = (unsigned)(e >> 32);
    unsigned bits = (hi & 0x80000000u) ? (hi & 0x7FFFFFFFu) : ~hi;
    g_colmin[c] = __uint_as_float(bits);
    int idx = (int)(0xFFFFFFFFu - (unsigned)(e & 0xFFFFFFFFull));
    atomicAdd(&g_cnt[idx], 1);
}

// ---------------- read = c_wr.T @ m_tm1, split-K with atomics -------------
// grid (4 btiles, 64 kchunks of 512 m), 256 thr, tile 64b x 128u, 8x4 micro.
__global__ void k_read(const float* __restrict__ m, const float* __restrict__ out_cwr,
                       float* __restrict__ out_read) {
    __shared__ float sA[32][64];
    __shared__ float sB[32][128];
    int t = threadIdx.x;
    int btile = blockIdx.x, kch = blockIdx.y;
    int tx = t & 31, bg = t >> 5;
    float acc[8][4];
    #pragma unroll
    for (int i = 0; i < 8; i++)
        #pragma unroll
        for (int j = 0; j < 4; j++) acc[i][j] = 0.f;

    for (int cc = 0; cc < 16; cc++) {
        int mb = kch * 512 + cc * 32;
        #pragma unroll
        for (int p = 0; p < 2; p++) {
            int i = t + p * 256;
            int r = i >> 4, c4 = (i & 15) * 4;
            *(float4*)&sA[r][c4] = *(const float4*)(out_cwr + (mb + r) * BATCH + btile * 64 + c4);
        }
        #pragma unroll
        for (int p = 0; p < 4; p++) {
            int i = t + p * 256;
            int r = i >> 5, c4 = (i & 31) * 4;
            *(float4*)&sB[r][c4] = *(const float4*)(m + (mb + r) * UNITS + c4);
        }
        __syncthreads();
        #pragma unroll 4
        for (int mm = 0; mm < 32; mm++) {
            float4 bv = *(float4*)&sB[mm][tx * 4];
            #pragma unroll
            for (int i = 0; i < 8; i++) {
                float a = sA[mm][bg * 8 + i];
                acc[i][0] += a * bv.x; acc[i][1] += a * bv.y;
                acc[i][2] += a * bv.z; acc[i][3] += a * bv.w;
            }
        }
        __syncthreads();
    }
    #pragma unroll
    for (int i = 0; i < 8; i++) {
        int b = btile * 64 + bg * 8 + i;
        #pragma unroll
        for (int j = 0; j < 4; j++)
            atomicAdd(&out_read[b * UNITS + tx * 4 + j], acc[i][j]);
    }
}

// ---------------- memory = c_ww @ h + (256 - cnt[m]) * m_tm1 --------------
// grid 512 mtiles, tile 64m x 128u, K=256 in chunks of 32, 8x4 micro.
__global__ void k_mem(const float* __restrict__ m, const float* __restrict__ out_cww,
                      float* __restrict__ out_mem) {
    __shared__ float sA[64][36];
    __shared__ float sB[32][128];
    int t = threadIdx.x;
    int mtile = blockIdx.x;
    int tx = t & 31, mg = t >> 5;
    float acc[8][4];
    #pragma unroll
    for (int i = 0; i < 8; i++)
        #pragma unroll
        for (int j = 0; j < 4; j++) acc[i][j] = 0.f;

    for (int kc = 0; kc < 8; kc++) {
        int kb = kc * 32;
        #pragma unroll
        for (int p = 0; p < 2; p++) {
            int i = t + p * 256;
            int r = i >> 3, c4 = (i & 7) * 4;
            *(float4*)&sA[r][c4] = *(const float4*)(out_cww + (mtile * 64 + r) * BATCH + kb + c4);
        }
        #pragma unroll
        for (int p = 0; p < 4; p++) {
            int i = t + p * 256;
            int r = i >> 5, c4 = (i & 31) * 4;
            *(float4*)&sB[r][c4] = *(const float4*)(g_h + (kb + r) * UNITS + c4);
        }
        __syncthreads();
        #pragma unroll 4
        for (int k = 0; k < 32; k++) {
            float4 bv = *(float4*)&sB[k][tx * 4];
            #pragma unroll
            for (int i = 0; i < 8; i++) {
                float a = sA[mg * 8 + i][k];
                acc[i][0] += a * bv.x; acc[i][1] += a * bv.y;
                acc[i][2] += a * bv.z; acc[i][3] += a * bv.w;
            }
        }
        __syncthreads();
    }
    #pragma unroll
    for (int i = 0; i < 8; i++) {
        int mr = mtile * 64 + mg * 8 + i;
        float f = (float)(BATCH - g_cnt[mr]);
        float4 mv = *(const float4*)(m + mr * UNITS + tx * 4);
        float4 o;
        o.x = acc[i][0] + f * mv.x;
        o.y = acc[i][1] + f * mv.y;
        o.z = acc[i][2] + f * mv.z;
        o.w = acc[i][3] + f * mv.w;
        *(float4*)(out_mem + mr * UNITS + tx * 4) = o;
    }
}

// ---------------- c_wlu = (c_wu <= colmin) ---------------- grid 2048 x 256
__global__ void k_wlu(const float* __restrict__ out_cwu, float* __restrict__ out_cwlu) {
    __shared__ float smin[256];
    smin[threadIdx.x] = g_colmin[threadIdx.x];
    __syncthreads();
    const int total = MEMN * BATCH / 4;
    for (int i4 = blockIdx.x * 256 + threadIdx.x; i4 < total; i4 += gridDim.x * 256) {
        float4 v = *(const float4*)(out_cwu + i4 * 4);
        int c = (i4 & 63) * 4;
        float4 o;
        o.x = (v.x <= smin[c])     ? 1.f : 0.f;
        o.y = (v.y <= smin[c + 1]) ? 1.f : 0.f;
        o.z = (v.z <= smin[c + 2]) ? 1.f : 0.f;
        o.w = (v.w <= smin[c + 3]) ? 1.f : 0.f;
        *(float4*)(out_cwlu + i4 * 4) = o;
    }
}

extern "C" void kernel_launch(void* const* d_in, const int* in_sizes, int n_in,
                              void* d_out, int out_size) {
    (void)in_sizes; (void)n_in; (void)out_size;
    const float* inputs   = (const float*)d_in[0];
    const float* r_tm1    = (const float*)d_in[1];
    const float* m_tm1    = (const float*)d_in[2];
    const float* c_wu_tm1 = (const float*)d_in[3];
    const float* c_wlu_tm1= (const float*)d_in[4];
    const float* c_wr_tm1 = (const float*)d_in[5];
    const float* c_ww_tm1 = (const float*)d_in[6];
    (void)c_ww_tm1;
    const float* h_tm1    = (const float*)d_in[7];
    const float* c_tm1    = (const float*)d_in[8];
    const float* Wk       = (const float*)d_in[9];
    const float* Wr       = (const float*)d_in[10];
    const float* bias     = (const float*)d_in[11];
    const float* wgate    = (const float*)d_in[12];
    float* out = (float*)d_out;

    k_init<<<128, 256>>>(out + OFF_READ);
    k_lstm<<<dim3(8, 16), 256>>>(inputs, r_tm1, h_tm1, c_tm1, Wk, Wr, bias, out);
    k_knorm<<<32, 256>>>();
    k_minv<<<4096, 256>>>(m_tm1);
    k_cos<<<dim3(4, 512), 256>>>(m_tm1);
    k_soft<<<256, 256>>>(c_wr_tm1, c_wlu_tm1, c_wu_tm1, wgate, out);
    k_argmin<<<1, 256>>>();
    k_read<<<dim3(4, 64), 256>>>(m_tm1, out + OFF_CWR, out + OFF_READ);
    k_mem<<<512, 256>>>(m_tm1, out + OFF_CWW, out + OFF_MEMORY);
    k_wlu<<<2048, 256>>>(out + OFF_CWU, out + OFF_CWLU);
}

// round 2
// speedup vs baseline: 1.0196x; 1.0196x over previous
#include <cuda_runtime.h>
#include <math.h>

#define MEMN 32768
#define BATCH 256
#define UNITS 128
#define IN_DIM 512

#define OFF_READ    0
#define OFF_MEMORY  (OFF_READ + BATCH*UNITS)
#define OFF_CWU     (OFF_MEMORY + MEMN*UNITS)
#define OFF_CWLU    (OFF_CWU + MEMN*BATCH)
#define OFF_CWR     (OFF_CWLU + MEMN*BATCH)
#define OFF_CWW     (OFF_CWR + MEMN*BATCH)
#define OFF_H       (OFF_CWW + MEMN*BATCH)
#define OFF_C       (OFF_H + BATCH*UNITS)

typedef unsigned long long ull;

// scratch (device globals: no allocation allowed)
__device__ float g_h[BATCH*UNITS];
__device__ float g_hT[UNITS*BATCH];          // [k][b]
__device__ float g_kinv[BATCH];
__device__ ull   g_colenc[BATCH];
__device__ float g_colmin[BATCH];
__device__ int   g_cnt[MEMN];

__device__ __forceinline__ unsigned ordf(float f) {
    unsigned u = __float_as_uint(f);
    return (u & 0x80000000u) ? ~u : (u | 0x80000000u);
}
__device__ __forceinline__ ull ffma2(ull a, ull b, ull c) {
    ull d;
    asm("fma.rn.f32x2 %0, %1, %2, %3;" : "=l"(d) : "l"(a), "l"(b), "l"(c));
    return d;
}
__device__ __forceinline__ float lo32(ull v) { return __uint_as_float((unsigned)v); }
__device__ __forceinline__ float hi32(ull v) { return __uint_as_float((unsigned)(v >> 32)); }

// ---------------- init ----------------
__global__ void k_init(float* __restrict__ out_read) {
    int i = blockIdx.x * 256 + threadIdx.x;
    if (i < MEMN) g_cnt[i] = 0;
    if (i < BATCH*UNITS) out_read[i] = 0.f;
    if (i < BATCH) g_colenc[i] = 0xFFFFFFFFFFFFFFFFull;
}

// ---------------- LSTM cell ----------------
__global__ void k_lstm(const float* __restrict__ inputs, const float* __restrict__ r_tm1,
                       const float* __restrict__ h_tm1, const float* __restrict__ c_tm1,
                       const float* __restrict__ Wk, const float* __restrict__ Wr,
                       const float* __restrict__ bias, float* __restrict__ out) {
    __shared__ float sA[16][128];
    __shared__ float sB[128][64];
    int t = threadIdx.x;
    int utile = blockIdx.x, btile = blockIdx.y;
    int ul = t & 15, bl = t >> 4;
    float acc[4] = {0.f, 0.f, 0.f, 0.f};

    for (int kc = 0; kc < 6; kc++) {
        #pragma unroll
        for (int p = 0; p < 2; p++) {
            int i = t + p * 256;
            int row = i >> 5, c4 = (i & 31) * 4;
            int b = btile * 16 + row;
            const float* src;
            if (kc < 4)       src = inputs + b * IN_DIM + kc * 128 + c4;
            else if (kc == 4) src = r_tm1 + b * UNITS + c4;
            else              src = h_tm1 + b * UNITS + c4;
            *(float4*)&sA[row][c4] = *(const float4*)src;
        }
        #pragma unroll
        for (int p = 0; p < 8; p++) {
            int i = t + p * 256;
            int k = i >> 4, c4 = (i & 15) * 4;
            int q = c4 >> 4, jr = c4 & 15;
            int jc = utile * 16 + jr + q * 128;
            float4 v;
            if (kc < 5) v = *(const float4*)(Wk + (kc * 128 + k) * 512 + jc);
            else        v = *(const float4*)(Wr + k * 512 + jc);
            *(float4*)&sB[k][c4] = v;
        }
        __syncthreads();
        #pragma unroll 8
        for (int k = 0; k < 128; k++) {
            float a = sA[bl][k];
            acc[0] += a * sB[k][ul];
            acc[1] += a * sB[k][16 + ul];
            acc[2] += a * sB[k][32 + ul];
            acc[3] += a * sB[k][48 + ul];
        }
        __syncthreads();
    }
    int b = btile * 16 + bl, u = utile * 16 + ul;
    float zi = acc[0] + bias[u];
    float zf = acc[1] + bias[128 + u];
    float zg = acc[2] + bias[256 + u];
    float zo = acc[3] + bias[384 + u];
    float si = 1.f / (1.f + expf(-zi));
    float sf = 1.f / (1.f + expf(-zf));
    float so = 1.f / (1.f + expf(-zo));
    float cn = sf * c_tm1[b * UNITS + u] + si * tanhf(zg);
    float hn = so * tanhf(cn);
    out[OFF_H + b * UNITS + u] = hn;
    out[OFF_C + b * UNITS + u] = cn;
    g_h[b * UNITS + u] = hn;
}

// ---------------- key inverse norms + h transpose ----------------
__global__ void k_knorm() {
    int t = threadIdx.x, w = t >> 5, l = t & 31;
    int b = blockIdx.x * 8 + w;
    float s = 0.f;
    #pragma unroll
    for (int i = 0; i < 4; i++) { float v = g_h[b * UNITS + l + 32 * i]; s += v * v; }
    #pragma unroll
    for (int o = 16; o; o >>= 1) s += __shfl_xor_sync(0xffffffffu, s, o);
    if (l == 0) g_kinv[b] = rsqrtf(fmaxf(s, 1e-12f));
    #pragma unroll
    for (int p = 0; p < 4; p++) {
        int idx = blockIdx.x * 1024 + p * 256 + t;
        g_hT[(idx & 127) * BATCH + (idx >> 7)] = g_h[idx];
    }
}

// ---------------- fused: row norms + cosine GEMM + softmax + ww/wu + col-min ---
// 1024 blocks, 32 m-rows x 256 batch each. FFMA2 mainloop.
// dyn smem layout: sA2 dup float2[128][32] (32KB) | sB float[32][256] (32KB)
//                  | sEnc ull[8][256] (16KB) | sSS float[256] | sMinv float[32]
__global__ void k_fuse(const float* __restrict__ m, const float* __restrict__ wr_tm1,
                       const float* __restrict__ wlu_tm1, const float* __restrict__ wu_tm1,
                       const float* __restrict__ wgate, float* __restrict__ out) {
    extern __shared__ char sm_[];
    float2* sA2 = (float2*)sm_;
    float*  sB  = (float*)(sm_ + 32768);
    ull*    sEnc = (ull*)(sm_ + 65536);
    float*  sSS = (float*)(sm_ + 81920);
    float*  sMinv = (float*)(sm_ + 82944);

    int t = threadIdx.x;
    int tx = t & 31, ty = t >> 5;
    int mbase = blockIdx.x * 32;

    // A load (dup pairs, [k][row]) + row sumsq
    {
        int arow = t >> 3;
        int kseg = (t & 7) * 16;
        const float* src = m + (mbase + arow) * UNITS + kseg;
        float ss = 0.f;
        #pragma unroll
        for (int p = 0; p < 4; p++) {
            float4 v = *(const float4*)(src + p * 4);
            int k = kseg + p * 4;
            sA2[(k + 0) * 32 + arow] = make_float2(v.x, v.x);
            sA2[(k + 1) * 32 + arow] = make_float2(v.y, v.y);
            sA2[(k + 2) * 32 + arow] = make_float2(v.z, v.z);
            sA2[(k + 3) * 32 + arow] = make_float2(v.w, v.w);
            ss += v.x * v.x + v.y * v.y + v.z * v.z + v.w * v.w;
        }
        sSS[t] = ss;
    }
    __syncthreads();
    if (t < 32) {
        float s = 0.f;
        #pragma unroll
        for (int q = 0; q < 8; q++) s += sSS[t * 8 + q];
        sMinv[t] = rsqrtf(fmaxf(s, 1e-12f));
    }

    ull acc[4][4];
    #pragma unroll
    for (int i = 0; i < 4; i++)
        #pragma unroll
        for (int j = 0; j < 4; j++) acc[i][j] = 0ull;

    for (int kc = 0; kc < 4; kc++) {
        int kb = kc * 32;
        #pragma unroll
        for (int p = 0; p < 8; p++) {
            int f = t + p * 256;
            int r = f >> 6, c4 = (f & 63) * 4;
            *(float4*)&sB[r * 256 + c4] = *(const float4*)(g_hT + (kb + r) * BATCH + c4);
        }
        __syncthreads();
        #pragma unroll 8
        for (int kk = 0; kk < 32; kk++) {
            int k = kb + kk;
            ull b0 = *(ull*)&sB[kk * 256 + 2 * tx];
            ull b1 = *(ull*)&sB[kk * 256 + 2 * tx + 64];
            ull b2 = *(ull*)&sB[kk * 256 + 2 * tx + 128];
            ull b3 = *(ull*)&sB[kk * 256 + 2 * tx + 192];
            #pragma unroll
            for (int i = 0; i < 4; i++) {
                ull a = *(ull*)&sA2[k * 32 + ty * 4 + i];
                acc[i][0] = ffma2(a, b0, acc[i][0]);
                acc[i][1] = ffma2(a, b1, acc[i][1]);
                acc[i][2] = ffma2(a, b2, acc[i][2]);
                acc[i][3] = ffma2(a, b3, acc[i][3]);
            }
        }
        __syncthreads();
    }

    // epilogue: scale to cosine, softmax per row (warp-wide), ww/wu, col-min enc
    float wg = 1.f / (1.f + __expf(-wgate[0]));
    float omw = 1.f - wg;
    float2 kin[4];
    #pragma unroll
    for (int j = 0; j < 4; j++) kin[j] = *(const float2*)&g_kinv[2 * tx + 64 * j];
    ull emin[8];
    #pragma unroll
    for (int j = 0; j < 8; j++) emin[j] = 0xFFFFFFFFFFFFFFFFull;

    #pragma unroll
    for (int i = 0; i < 4; i++) {
        int rloc = ty * 4 + i;
        int r = mbase + rloc;
        float mi = sMinv[rloc];
        float x[8];
        #pragma unroll
        for (int j = 0; j < 4; j++) {
            x[2 * j]     = lo32(acc[i][j]) * mi * kin[j].x;
            x[2 * j + 1] = hi32(acc[i][j]) * mi * kin[j].y;
        }
        float mx = x[0];
        #pragma unroll
        for (int jj = 1; jj < 8; jj++) mx = fmaxf(mx, x[jj]);
        #pragma unroll
        for (int o = 16; o; o >>= 1) mx = fmaxf(mx, __shfl_xor_sync(0xffffffffu, mx, o));
        float e[8], s = 0.f;
        #pragma unroll
        for (int jj = 0; jj < 8; jj++) { e[jj] = __expf(x[jj] - mx); s += e[jj]; }
        #pragma unroll
        for (int o = 16; o; o >>= 1) s += __shfl_xor_sync(0xffffffffu, s, o);
        float inv = 1.f / s;
        ull lw = (ull)(0xFFFFFFFFu - (unsigned)r);
        #pragma unroll
        for (int j = 0; j < 4; j++) {
            int c0 = 2 * tx + 64 * j;
            int idx = r * BATCH + c0;
            float2 wrp = make_float2(e[2 * j] * inv, e[2 * j + 1] * inv);
            float2 wrt = *(const float2*)&wr_tm1[idx];
            float2 wlt = *(const float2*)&wlu_tm1[idx];
            float2 wut = *(const float2*)&wu_tm1[idx];
            float2 ww = make_float2(wg * wrt.x + omw + wlt.x, wg * wrt.y + omw + wlt.y);
            float2 wu = make_float2(0.95f * wut.x + wrp.x + ww.x, 0.95f * wut.y + wrp.y + ww.y);
            *(float2*)&out[OFF_CWR + idx] = wrp;
            *(float2*)&out[OFF_CWW + idx] = ww;
            *(float2*)&out[OFF_CWU + idx] = wu;
            ull e0 = ((ull)ordf(wu.x) << 32) | lw;
            ull e1 = ((ull)ordf(wu.y) << 32) | lw;
            emin[2 * j]     = (e0 < emin[2 * j])     ? e0 : emin[2 * j];
            emin[2 * j + 1] = (e1 < emin[2 * j + 1]) ? e1 : emin[2 * j + 1];
        }
    }
    #pragma unroll
    for (int j = 0; j < 4; j++) {
        sEnc[ty * 256 + 2 * tx + 64 * j]     = emin[2 * j];
        sEnc[ty * 256 + 2 * tx + 64 * j + 1] = emin[2 * j + 1];
    }
    __syncthreads();
    {
        ull e2 = sEnc[t];
        #pragma unroll
        for (int w = 1; w < 8; w++) { ull v = sEnc[w * 256 + t]; e2 = (v < e2) ? v : e2; }
        atomicMin(&g_colenc[t], e2);
    }
}

// ---------------- finalize argmin ---------------- 1 x 256
__global__ void k_fin() {
    int c = threadIdx.x;
    ull e = g_colenc[c];
    unsigned hi = (unsigned)(e >> 32);
    unsigned bits = (hi & 0x80000000u) ? (hi & 0x7FFFFFFFu) : ~hi;
    g_colmin[c] = __uint_as_float(bits);
    int idx = (int)(0xFFFFFFFFu - (unsigned)(e & 0xFFFFFFFFull));
    atomicAdd(&g_cnt[idx], 1);
}

// ---------------- read = c_wr.T @ m_tm1, split-K, FFMA2 -------------
// grid (4 btiles, 64 kchunks), 256 thr, tile 64b x 128u, 8x4 micro.
__global__ void k_read(const float* __restrict__ m, const float* __restrict__ cwr,
                       float* __restrict__ out_read) {
    __shared__ float2 sA2[32 * 64];   // dup [mm][bcol]
    __shared__ float  sB[32 * 128];
    int t = threadIdx.x;
    int btile = blockIdx.x, kch = blockIdx.y;
    int tx = t & 31, bg = t >> 5;
    ull acc[8][2];
    #pragma unroll
    for (int i = 0; i < 8; i++) { acc[i][0] = 0ull; acc[i][1] = 0ull; }

    for (int cc = 0; cc < 16; cc++) {
        int mb = kch * 512 + cc * 32;
        #pragma unroll
        for (int p = 0; p < 2; p++) {
            int f = t + p * 256;
            int r = f >> 4, c4 = (f & 15) * 4;
            float4 v = *(const float4*)(cwr + (mb + r) * BATCH + btile * 64 + c4);
            sA2[r * 64 + c4 + 0] = make_float2(v.x, v.x);
            sA2[r * 64 + c4 + 1] = make_float2(v.y, v.y);
            sA2[r * 64 + c4 + 2] = make_float2(v.z, v.z);
            sA2[r * 64 + c4 + 3] = make_float2(v.w, v.w);
        }
        #pragma unroll
        for (int p = 0; p < 4; p++) {
            int f = t + p * 256;
            int r = f >> 5, c4 = (f & 31) * 4;
            *(float4*)&sB[r * 128 + c4] = *(const float4*)(m + (mb + r) * UNITS + c4);
        }
        __syncthreads();
        #pragma unroll 8
        for (int mm = 0; mm < 32; mm++) {
            longlong2 db = *(longlong2*)&sB[mm * 128 + tx * 4];
            ull b0 = (ull)db.x, b1 = (ull)db.y;
            #pragma unroll
            for (int i = 0; i < 8; i++) {
                ull a = *(ull*)&sA2[mm * 64 + bg * 8 + i];
                acc[i][0] = ffma2(a, b0, acc[i][0]);
                acc[i][1] = ffma2(a, b1, acc[i][1]);
            }
        }
        __syncthreads();
    }
    #pragma unroll
    for (int i = 0; i < 8; i++) {
        int b = btile * 64 + bg * 8 + i;
        atomicAdd(&out_read[b * UNITS + tx * 4 + 0], lo32(acc[i][0]));
        atomicAdd(&out_read[b * UNITS + tx * 4 + 1], hi32(acc[i][0]));
        atomicAdd(&out_read[b * UNITS + tx * 4 + 2], lo32(acc[i][1]));
        atomicAdd(&out_read[b * UNITS + tx * 4 + 3], hi32(acc[i][1]));
    }
}

// ---------------- memory = c_ww @ h + (256 - cnt[m]) * m_tm1, FFMA2 ---------
// grid 512 mtiles, tile 64m x 128u, 8x4 micro.
__global__ void k_mem(const float* __restrict__ m, const float* __restrict__ cww,
                      float* __restrict__ out_mem) {
    __shared__ float2 sA2[64 * 32];   // dup [mrow][k]
    __shared__ float  sB[32 * 128];
    int t = threadIdx.x;
    int mtile = blockIdx.x;
    int tx = t & 31, mg = t >> 5;
    ull acc[8][2];
    #pragma unroll
    for (int i = 0; i < 8; i++) { acc[i][0] = 0ull; acc[i][1] = 0ull; }

    for (int kc = 0; kc < 8; kc++) {
        int kb = kc * 32;
        #pragma unroll
        for (int p = 0; p < 2; p++) {
            int f = t + p * 256;
            int r = f >> 3, c4 = (f & 7) * 4;
            float4 v = *(const float4*)(cww + (mtile * 64 + r) * BATCH + kb + c4);
            sA2[r * 32 + c4 + 0] = make_float2(v.x, v.x);
            sA2[r * 32 + c4 + 1] = make_float2(v.y, v.y);
            sA2[r * 32 + c4 + 2] = make_float2(v.z, v.z);
            sA2[r * 32 + c4 + 3] = make_float2(v.w, v.w);
        }
        #pragma unroll
        for (int p = 0; p < 4; p++) {
            int f = t + p * 256;
            int r = f >> 5, c4 = (f & 31) * 4;
            *(float4*)&sB[r * 128 + c4] = *(const float4*)(g_h + (kb + r) * UNITS + c4);
        }
        __syncthreads();
        #pragma unroll 8
        for (int k = 0; k < 32; k++) {
            longlong2 db = *(longlong2*)&sB[k * 128 + tx * 4];
            ull b0 = (ull)db.x, b1 = (ull)db.y;
            #pragma unroll
            for (int i = 0; i < 8; i++) {
                ull a = *(ull*)&sA2[(mg * 8 + i) * 32 + k];
                acc[i][0] = ffma2(a, b0, acc[i][0]);
                acc[i][1] = ffma2(a, b1, acc[i][1]);
            }
        }
        __syncthreads();
    }
    #pragma unroll
    for (int i = 0; i < 8; i++) {
        int mr = mtile * 64 + mg * 8 + i;
        float f = (float)(BATCH - g_cnt[mr]);
        float4 mv = *(const float4*)(m + mr * UNITS + tx * 4);
        float4 o;
        o.x = lo32(acc[i][0]) + f * mv.x;
        o.y = hi32(acc[i][0]) + f * mv.y;
        o.z = lo32(acc[i][1]) + f * mv.z;
        o.w = hi32(acc[i][1]) + f * mv.w;
        *(float4*)(out_mem + mr * UNITS + tx * 4) = o;
    }
}

// ---------------- c_wlu = (c_wu <= colmin) ----------------
__global__ void k_wlu(const float* __restrict__ out_cwu, float* __restrict__ out_cwlu) {
    __shared__ float smin[256];
    smin[threadIdx.x] = g_colmin[threadIdx.x];
    __syncthreads();
    const int total = MEMN * BATCH / 4;
    for (int i4 = blockIdx.x * 256 + threadIdx.x; i4 < total; i4 += gridDim.x * 256) {
        float4 v = *(const float4*)(out_cwu + i4 * 4);
        int c = (i4 & 63) * 4;
        float4 o;
        o.x = (v.x <= smin[c])     ? 1.f : 0.f;
        o.y = (v.y <= smin[c + 1]) ? 1.f : 0.f;
        o.z = (v.z <= smin[c + 2]) ? 1.f : 0.f;
        o.w = (v.w <= smin[c + 3]) ? 1.f : 0.f;
        *(float4*)(out_cwlu + i4 * 4) = o;
    }
}

extern "C" void kernel_launch(void* const* d_in, const int* in_sizes, int n_in,
                              void* d_out, int out_size) {
    (void)in_sizes; (void)n_in; (void)out_size;
    const float* inputs   = (const float*)d_in[0];
    const float* r_tm1    = (const float*)d_in[1];
    const float* m_tm1    = (const float*)d_in[2];
    const float* c_wu_tm1 = (const float*)d_in[3];
    const float* c_wlu_tm1= (const float*)d_in[4];
    const float* c_wr_tm1 = (const float*)d_in[5];
    const float* h_tm1    = (const float*)d_in[7];
    const float* c_tm1    = (const float*)d_in[8];
    const float* Wk       = (const float*)d_in[9];
    const float* Wr       = (const float*)d_in[10];
    const float* bias     = (const float*)d_in[11];
    const float* wgate    = (const float*)d_in[12];
    float* out = (float*)d_out;

    cudaFuncSetAttribute(k_fuse, cudaFuncAttributeMaxDynamicSharedMemorySize, 83072);

    k_init<<<128, 256>>>(out + OFF_READ);
    k_lstm<<<dim3(8, 16), 256>>>(inputs, r_tm1, h_tm1, c_tm1, Wk, Wr, bias, out);
    k_knorm<<<32, 256>>>();
    k_fuse<<<1024, 256, 83072>>>(m_tm1, c_wr_tm1, c_wlu_tm1, c_wu_tm1, wgate, out);
    k_fin<<<1, 256>>>();
    k_read<<<dim3(4, 64), 256>>>(m_tm1, out + OFF_CWR, out + OFF_READ);
    k_mem<<<512, 256>>>(m_tm1, out + OFF_CWW, out + OFF_MEMORY);
    k_wlu<<<2048, 256>>>(out + OFF_CWU, out + OFF_CWLU);
}

// round 5
// speedup vs baseline: 1.0691x; 1.0485x over previous
#include <cuda_runtime.h>
#include <math.h>
#include <stdint.h>

#define MEMN 32768
#define BATCH 256
#define UNITS 128
#define IN_DIM 512

#define OFF_READ    0
#define OFF_MEMORY  (OFF_READ + BATCH*UNITS)
#define OFF_CWU     (OFF_MEMORY + MEMN*UNITS)
#define OFF_CWLU    (OFF_CWU + MEMN*BATCH)
#define OFF_CWR     (OFF_CWLU + MEMN*BATCH)
#define OFF_CWW     (OFF_CWR + MEMN*BATCH)
#define OFF_H       (OFF_CWW + MEMN*BATCH)
#define OFF_C       (OFF_H + BATCH*UNITS)

#define PA 132
#define PB 136

typedef unsigned long long ull;

// scratch (device globals: no allocation allowed)
__device__ float g_h[BATCH*UNITS];
__device__ float g_hT[UNITS*BATCH];          // [unit][batch]
__device__ float g_kinv[BATCH];
__device__ float g_cos[MEMN*BATCH];          // 32MB scratch (minv pre-applied)
__device__ ull   g_part[256*256];
__device__ float g_colmin[BATCH];
__device__ int   g_cnt[MEMN];

__device__ __forceinline__ unsigned ordf(float f) {
    unsigned u = __float_as_uint(f);
    return (u & 0x80000000u) ? ~u : (u | 0x80000000u);
}

__device__ __forceinline__ void mma_tf32(float* d, const unsigned* a, const unsigned* b) {
    asm volatile(
        "mma.sync.aligned.m16n8k8.row.col.f32.tf32.tf32.f32 "
        "{%0,%1,%2,%3}, {%4,%5,%6,%7}, {%8,%9}, {%0,%1,%2,%3};"
        : "+f"(d[0]), "+f"(d[1]), "+f"(d[2]), "+f"(d[3])
        : "r"(a[0]), "r"(a[1]), "r"(a[2]), "r"(a[3]), "r"(b[0]), "r"(b[1]));
}

__device__ __forceinline__ void split_tf32(float a, unsigned& hi, unsigned& lo) {
    unsigned u = __float_as_uint(a) & 0xffffe000u;   // exact tf32 (trunc)
    hi = u;
    lo = __float_as_uint(a - __uint_as_float(u));    // residual, exact in fp32
}

// ---------------- init ----------------
__global__ void k_init(float* __restrict__ out_read) {
    int i = blockIdx.x * 256 + threadIdx.x;
    if (i < MEMN) g_cnt[i] = 0;
    if (i < BATCH*UNITS) out_read[i] = 0.f;
}

// ---------------- LSTM cell ----------------
__global__ void k_lstm(const float* __restrict__ inputs, const float* __restrict__ r_tm1,
                       const float* __restrict__ h_tm1, const float* __restrict__ c_tm1,
                       const float* __restrict__ Wk, const float* __restrict__ Wr,
                       const float* __restrict__ bias, float* __restrict__ out) {
    __shared__ float sA[16][128];
    __shared__ float sB[128][64];
    int t = threadIdx.x;
    int utile = blockIdx.x, btile = blockIdx.y;
    int ul = t & 15, bl = t >> 4;
    float acc[4] = {0.f, 0.f, 0.f, 0.f};

    for (int kc = 0; kc < 6; kc++) {
        #pragma unroll
        for (int p = 0; p < 2; p++) {
            int i = t + p * 256;
            int row = i >> 5, c4 = (i & 31) * 4;
            int b = btile * 16 + row;
            const float* src;
            if (kc < 4)       src = inputs + b * IN_DIM + kc * 128 + c4;
            else if (kc == 4) src = r_tm1 + b * UNITS + c4;
            else              src = h_tm1 + b * UNITS + c4;
            *(float4*)&sA[row][c4] = *(const float4*)src;
        }
        #pragma unroll
        for (int p = 0; p < 8; p++) {
            int i = t + p * 256;
            int k = i >> 4, c4 = (i & 15) * 4;
            int q = c4 >> 4, jr = c4 & 15;
            int jc = utile * 16 + jr + q * 128;
            float4 v;
            if (kc < 5) v = *(const float4*)(Wk + (kc * 128 + k) * 512 + jc);
            else        v = *(const float4*)(Wr + k * 512 + jc);
            *(float4*)&sB[k][c4] = v;
        }
        __syncthreads();
        #pragma unroll 8
        for (int k = 0; k < 128; k++) {
            float a = sA[bl][k];
            acc[0] += a * sB[k][ul];
            acc[1] += a * sB[k][16 + ul];
            acc[2] += a * sB[k][32 + ul];
            acc[3] += a * sB[k][48 + ul];
        }
        __syncthreads();
    }
    int b = btile * 16 + bl, u = utile * 16 + ul;
    float zi = acc[0] + bias[u];
    float zf = acc[1] + bias[128 + u];
    float zg = acc[2] + bias[256 + u];
    float zo = acc[3] + bias[384 + u];
    float si = 1.f / (1.f + expf(-zi));
    float sf = 1.f / (1.f + expf(-zf));
    float so = 1.f / (1.f + expf(-zo));
    float cn = sf * c_tm1[b * UNITS + u] + si * tanhf(zg);
    float hn = so * tanhf(cn);
    out[OFF_H + b * UNITS + u] = hn;
    out[OFF_C + b * UNITS + u] = cn;
    g_h[b * UNITS + u] = hn;
}

// ---------------- key inverse norms + h transpose ----------------
__global__ void k_knorm() {
    int t = threadIdx.x, w = t >> 5, l = t & 31;
    int b = blockIdx.x * 8 + w;
    float s = 0.f;
    #pragma unroll
    for (int i = 0; i < 4; i++) { float v = g_h[b * UNITS + l + 32 * i]; s += v * v; }
    #pragma unroll
    for (int o = 16; o; o >>= 1) s += __shfl_xor_sync(0xffffffffu, s, o);
    if (l == 0) g_kinv[b] = rsqrtf(fmaxf(s, 1e-12f));
    #pragma unroll
    for (int p = 0; p < 4; p++) {
        int idx = blockIdx.x * 1024 + p * 256 + t;
        g_hT[(idx & 127) * BATCH + (idx >> 7)] = g_h[idx];
    }
}

// ---------------- cosine GEMM, tf32 tensor core, 3-way split --------------
// grid (2 ntiles, 256 mtiles), 256 thr. CTA tile 128m x 128n, K=128.
__global__ void __launch_bounds__(256) k_cos(const float* __restrict__ mptr) {
    extern __shared__ float sm[];
    float* sA = sm;                      // [128][PA]
    float* sB = sm + 128 * PA;           // [128][PB]
    float* sSS = sB + 128 * PB;          // [128] minv

    int t = threadIdx.x;
    int lane = t & 31, wid = t >> 5;
    int qr = lane >> 2, qc = lane & 3;
    int nbase = blockIdx.x * 128, mbase = blockIdx.y * 128;

    #pragma unroll
    for (int i = 0; i < 16; i++) {
        int g = t + i * 256;
        int r = g >> 5, c4 = (g & 31) << 2;
        *(float4*)&sA[r * PA + c4] = *(const float4*)(mptr + (mbase + r) * UNITS + c4);
        *(float4*)&sB[r * PB + c4] = *(const float4*)(g_hT + r * BATCH + nbase + c4);
    }
    __syncthreads();
    if (t < 128) {
        float ss = 0.f;
        #pragma unroll
        for (int i = 0; i < 32; i++) {
            float4 v = *(float4*)&sA[t * PA + i * 4];
            ss += v.x * v.x + v.y * v.y + v.z * v.z + v.w * v.w;
        }
        sSS[t] = rsqrtf(fmaxf(ss, 1e-12f));
    }
    __syncthreads();

    int wm = (wid >> 1) * 32, wn = (wid & 1) * 64;
    float acc[2][8][4];
    #pragma unroll
    for (int i = 0; i < 2; i++)
        #pragma unroll
        for (int j = 0; j < 8; j++)
            #pragma unroll
            for (int q = 0; q < 4; q++) acc[i][j][q] = 0.f;

    for (int ks = 0; ks < 16; ks++) {
        int kb = ks * 8;
        unsigned ah[2][4], al[2][4], bh[8][2], bl[8][2];
        #pragma unroll
        for (int mt = 0; mt < 2; mt++) {
            int rb = wm + mt * 16;
            split_tf32(sA[(rb + qr) * PA + kb + qc],       ah[mt][0], al[mt][0]);
            split_tf32(sA[(rb + 8 + qr) * PA + kb + qc],   ah[mt][1], al[mt][1]);
            split_tf32(sA[(rb + qr) * PA + kb + 4 + qc],   ah[mt][2], al[mt][2]);
            split_tf32(sA[(rb + 8 + qr) * PA + kb + 4 + qc], ah[mt][3], al[mt][3]);
        }
        #pragma unroll
        for (int nt = 0; nt < 8; nt++) {
            int cb = wn + nt * 8;
            split_tf32(sB[(kb + qc) * PB + cb + qr],     bh[nt][0], bl[nt][0]);
            split_tf32(sB[(kb + 4 + qc) * PB + cb + qr], bh[nt][1], bl[nt][1]);
        }
        #pragma unroll
        for (int mt = 0; mt < 2; mt++)
            #pragma unroll
            for (int nt = 0; nt < 8; nt++) {
                mma_tf32(acc[mt][nt], ah[mt], bh[nt]);
                mma_tf32(acc[mt][nt], al[mt], bh[nt]);
                mma_tf32(acc[mt][nt], ah[mt], bl[nt]);
            }
    }

    #pragma unroll
    for (int mt = 0; mt < 2; mt++) {
        int r0 = wm + mt * 16 + qr;
        float s0 = sSS[r0], s1 = sSS[r0 + 8];
        #pragma unroll
        for (int nt = 0; nt < 8; nt++) {
            int c = wn + nt * 8 + 2 * qc;
            float2 o0 = make_float2(acc[mt][nt][0] * s0, acc[mt][nt][1] * s0);
            float2 o1 = make_float2(acc[mt][nt][2] * s1, acc[mt][nt][3] * s1);
            *(float2*)&g_cos[(mbase + r0) * BATCH + nbase + c] = o0;
            *(float2*)&g_cos[(mbase + r0 + 8) * BATCH + nbase + c] = o1;
        }
    }
}

// ---------------- softmax + c_ww + c_wu + per-column min partials ----------
__global__ void k_soft(const float* __restrict__ wr_tm1, const float* __restrict__ wlu_tm1,
                       const float* __restrict__ wu_tm1, const float* __restrict__ wgate,
                       float* __restrict__ out) {
    __shared__ ull s_enc[8][256];
    __shared__ float sKinv[256];
    int t = threadIdx.x, w = t >> 5, l = t & 31;
    sKinv[t] = g_kinv[t];
    __syncthreads();
    float wg = 1.f / (1.f + __expf(-wgate[0]));
    float omw = 1.f - wg;
    ull emin[8];
    #pragma unroll
    for (int j = 0; j < 8; j++) emin[j] = 0xFFFFFFFFFFFFFFFFull;

    for (int i = 0; i < 16; i++) {
        int r = blockIdx.x * 128 + w * 16 + i;
        float x[8];
        #pragma unroll
        for (int j = 0; j < 8; j++) x[j] = g_cos[r * BATCH + l + 32 * j] * sKinv[l + 32 * j];
        float mx = x[0];
        #pragma unroll
        for (int j = 1; j < 8; j++) mx = fmaxf(mx, x[j]);
        #pragma unroll
        for (int o = 16; o; o >>= 1) mx = fmaxf(mx, __shfl_xor_sync(0xffffffffu, mx, o));
        float e[8], s = 0.f;
        #pragma unroll
        for (int j = 0; j < 8; j++) { e[j] = __expf(x[j] - mx); s += e[j]; }
        #pragma unroll
        for (int o = 16; o; o >>= 1) s += __shfl_xor_sync(0xffffffffu, s, o);
        float inv = 1.f / s;
        #pragma unroll
        for (int j = 0; j < 8; j++) {
            int c = l + 32 * j;
            int idx = r * BATCH + c;
            float wr = e[j] * inv;
            float ww = wg * wr_tm1[idx] + omw + wlu_tm1[idx];
            float wu = 0.95f * wu_tm1[idx] + wr + ww;
            out[OFF_CWR + idx] = wr;
            out[OFF_CWW + idx] = ww;
            out[OFF_CWU + idx] = wu;
            ull enc = ((ull)ordf(wu) << 32)
                    | (ull)(0xFFFFFFFFu - (unsigned)r);
            emin[j] = (enc < emin[j]) ? enc : emin[j];
        }
    }
    #pragma unroll
    for (int j = 0; j < 8; j++) s_enc[w][l + 32 * j] = emin[j];
    __syncthreads();
    ull e = s_enc[0][t];
    #pragma unroll
    for (int w2 = 1; w2 < 8; w2++) { ull v = s_enc[w2][t]; e = (v < e) ? v : e; }
    g_part[blockIdx.x * 256 + t] = e;
}

// ---------------- argmin finalize ---------------- 1 x 256
__global__ void k_argmin() {
    int c = threadIdx.x;
    ull e = 0xFFFFFFFFFFFFFFFFull;
    for (int i = 0; i < 256; i++) {
        ull v = g_part[i * 256 + c];
        e = (v < e) ? v : e;
    }
    unsigned hi = (unsigned)(e >> 32);
    unsigned bits = (hi & 0x80000000u) ? (hi & 0x7FFFFFFFu) : ~hi;
    g_colmin[c] = __uint_as_float(bits);
    int idx = (int)(0xFFFFFFFFu - (unsigned)(e & 0xFFFFFFFFull));
    atomicAdd(&g_cnt[idx], 1);
}

// ---------------- read = c_wr.T @ m_tm1, tf32 TC + 3-split, split-K --------
// grid (2 btiles, 32 kchunks of 1024), 256 thr. CTA 128b x 128u.
__global__ void __launch_bounds__(256) k_read(const float* __restrict__ mptr,
                                              const float* __restrict__ cwr,
                                              float* __restrict__ out_read) {
    extern __shared__ float sm[];
    float* sW = sm;                  // [64][PB]  wr chunk [k][b]
    float* sM = sm + 64 * PB;        // [64][PB]  m chunk [k][u]

    int t = threadIdx.x;
    int lane = t & 31, wid = t >> 5;
    int qr = lane >> 2, qc = lane & 3;
    int bbase = blockIdx.x * 128;
    int kchunk = blockIdx.y;
    int wm = (wid >> 1) * 32, wn = (wid & 1) * 64;

    float acc[2][8][4];
    #pragma unroll
    for (int i = 0; i < 2; i++)
        #pragma unroll
        for (int j = 0; j < 8; j++)
            #pragma unroll
            for (int q = 0; q < 4; q++) acc[i][j][q] = 0.f;

    for (int it = 0; it < 16; it++) {
        int kb0 = kchunk * 1024 + it * 64;
        #pragma unroll
        for (int i = 0; i < 8; i++) {
            int g = t + i * 256;
            int r = g >> 5, c4 = (g & 31) << 2;
            *(float4*)&sW[r * PB + c4] = *(const float4*)(cwr + (kb0 + r) * BATCH + bbase + c4);
            *(float4*)&sM[r * PB + c4] = *(const float4*)(mptr + (kb0 + r) * UNITS + c4);
        }
        __syncthreads();
        #pragma unroll
        for (int ks = 0; ks < 8; ks++) {
            int kb = ks * 8;
            unsigned ah[2][4], al[2][4], bh[8][2], bl[8][2];
            #pragma unroll
            for (int mt = 0; mt < 2; mt++) {
                int rb = wm + mt * 16;
                split_tf32(sW[(kb + qc) * PB + rb + qr],         ah[mt][0], al[mt][0]);
                split_tf32(sW[(kb + qc) * PB + rb + 8 + qr],     ah[mt][1], al[mt][1]);
                split_tf32(sW[(kb + 4 + qc) * PB + rb + qr],     ah[mt][2], al[mt][2]);
                split_tf32(sW[(kb + 4 + qc) * PB + rb + 8 + qr], ah[mt][3], al[mt][3]);
            }
            #pragma unroll
            for (int nt = 0; nt < 8; nt++) {
                int cb = wn + nt * 8;
                split_tf32(sM[(kb + qc) * PB + cb + qr],     bh[nt][0], bl[nt][0]);
                split_tf32(sM[(kb + 4 + qc) * PB + cb + qr], bh[nt][1], bl[nt][1]);
            }
            #pragma unroll
            for (int mt = 0; mt < 2; mt++)
                #pragma unroll
                for (int nt = 0; nt < 8; nt++) {
                    mma_tf32(acc[mt][nt], ah[mt], bh[nt]);
                    mma_tf32(acc[mt][nt], al[mt], bh[nt]);
                    mma_tf32(acc[mt][nt], ah[mt], bl[nt]);
                }
        }
        __syncthreads();
    }
    #pragma unroll
    for (int mt = 0; mt < 2; mt++) {
        int r0 = bbase + wm + mt * 16 + qr;
        #pragma unroll
        for (int nt = 0; nt < 8; nt++) {
            int c = wn + nt * 8 + 2 * qc;
            atomicAdd(&out_read[r0 * UNITS + c],           acc[mt][nt][0]);
            atomicAdd(&out_read[r0 * UNITS + c + 1],       acc[mt][nt][1]);
            atomicAdd(&out_read[(r0 + 8) * UNITS + c],     acc[mt][nt][2]);
            atomicAdd(&out_read[(r0 + 8) * UNITS + c + 1], acc[mt][nt][3]);
        }
    }
}

// ---------------- memory = c_ww @ h + (256 - cnt[m]) * m_tm1, tf32 3-split --
// grid 256 mtiles, 256 thr. CTA 128m x 128u, K=256 in 2 halves.
__global__ void __launch_bounds__(256) k_mem(const float* __restrict__ mptr,
                                             const float* __restrict__ cww,
                                             float* __restrict__ out_mem) {
    extern __shared__ float sm[];
    float* sA = sm;                  // [128][PA]  cww half [row][k]
    float* sB = sm + 128 * PA;       // [128][PB]  h half [k=b][u]

    int t = threadIdx.x;
    int lane = t & 31, wid = t >> 5;
    int qr = lane >> 2, qc = lane & 3;
    int mbase = blockIdx.x * 128;
    int wm = (wid >> 1) * 32, wn = (wid & 1) * 64;

    float acc[2][8][4];
    #pragma unroll
    for (int i = 0; i < 2; i++)
        #pragma unroll
        for (int j = 0; j < 8; j++)
            #pragma unroll
            for (int q = 0; q < 4; q++) acc[i][j][q] = 0.f;

    for (int kc = 0; kc < 2; kc++) {
        #pragma unroll
        for (int i = 0; i < 16; i++) {
            int g = t + i * 256;
            int r = g >> 5, c4 = (g & 31) << 2;
            *(float4*)&sA[r * PA + c4] = *(const float4*)(cww + (mbase + r) * BATCH + kc * 128 + c4);
            *(float4*)&sB[r * PB + c4] = *(const float4*)(g_h + (kc * 128 + r) * UNITS + c4);
        }
        __syncthreads();
        #pragma unroll
        for (int ks = 0; ks < 16; ks++) {
            int kb = ks * 8;
            unsigned ah[2][4], al[2][4], bh[8][2], bl[8][2];
            #pragma unroll
            for (int mt = 0; mt < 2; mt++) {
                int rb = wm + mt * 16;
                split_tf32(sA[(rb + qr) * PA + kb + qc],         ah[mt][0], al[mt][0]);
                split_tf32(sA[(rb + 8 + qr) * PA + kb + qc],     ah[mt][1], al[mt][1]);
                split_tf32(sA[(rb + qr) * PA + kb + 4 + qc],     ah[mt][2], al[mt][2]);
                split_tf32(sA[(rb + 8 + qr) * PA + kb + 4 + qc], ah[mt][3], al[mt][3]);
            }
            #pragma unroll
            for (int nt = 0; nt < 8; nt++) {
                int cb = wn + nt * 8;
                split_tf32(sB[(kb + qc) * PB + cb + qr],     bh[nt][0], bl[nt][0]);
                split_tf32(sB[(kb + 4 + qc) * PB + cb + qr], bh[nt][1], bl[nt][1]);
            }
            #pragma unroll
            for (int mt = 0; mt < 2; mt++)
                #pragma unroll
                for (int nt = 0; nt < 8; nt++) {
                    mma_tf32(acc[mt][nt], ah[mt], bh[nt]);
                    mma_tf32(acc[mt][nt], al[mt], bh[nt]);
                    mma_tf32(acc[mt][nt], ah[mt], bl[nt]);
                }
        }
        __syncthreads();
    }

    #pragma unroll
    for (int mt = 0; mt < 2; mt++) {
        int r0 = mbase + wm + mt * 16 + qr;
        float f0 = (float)(BATCH - g_cnt[r0]);
        float f1 = (float)(BATCH - g_cnt[r0 + 8]);
        #pragma unroll
        for (int nt = 0; nt < 8; nt++) {
            int c = wn + nt * 8 + 2 * qc;
            float2 m0 = *(const float2*)(mptr + r0 * UNITS + c);
            float2 m1 = *(const float2*)(mptr + (r0 + 8) * UNITS + c);
            float2 o0 = make_float2(acc[mt][nt][0] + f0 * m0.x, acc[mt][nt][1] + f0 * m0.y);
            float2 o1 = make_float2(acc[mt][nt][2] + f1 * m1.x, acc[mt][nt][3] + f1 * m1.y);
            *(float2*)(out_mem + r0 * UNITS + c) = o0;
            *(float2*)(out_mem + (r0 + 8) * UNITS + c) = o1;
        }
    }
}

// ---------------- c_wlu = (c_wu <= colmin) ----------------
__global__ void k_wlu(const float* __restrict__ out_cwu, float* __restrict__ out_cwlu) {
    __shared__ float smin[256];
    smin[threadIdx.x] = g_colmin[threadIdx.x];
    __syncthreads();
    const int total = MEMN * BATCH / 4;
    for (int i4 = blockIdx.x * 256 + threadIdx.x; i4 < total; i4 += gridDim.x * 256) {
        float4 v = *(const float4*)(out_cwu + i4 * 4);
        int c = (i4 & 63) * 4;
        float4 o;
        o.x = (v.x <= smin[c])     ? 1.f : 0.f;
        o.y = (v.y <= smin[c + 1]) ? 1.f : 0.f;
        o.z = (v.z <= smin[c + 2]) ? 1.f : 0.f;
        o.w = (v.w <= smin[c + 3]) ? 1.f : 0.f;
        *(float4*)(out_cwlu + i4 * 4) = o;
    }
}

extern "C" void kernel_launch(void* const* d_in, const int* in_sizes, int n_in,
                              void* d_out, int out_size) {
    (void)in_sizes; (void)n_in; (void)out_size;
    const float* inputs   = (const float*)d_in[0];
    const float* r_tm1    = (const float*)d_in[1];
    const float* m_tm1    = (const float*)d_in[2];
    const float* c_wu_tm1 = (const float*)d_in[3];
    const float* c_wlu_tm1= (const float*)d_in[4];
    const float* c_wr_tm1 = (const float*)d_in[5];
    const float* h_tm1    = (const float*)d_in[7];
    const float* c_tm1    = (const float*)d_in[8];
    const float* Wk       = (const float*)d_in[9];
    const float* Wr       = (const float*)d_in[10];
    const float* bias     = (const float*)d_in[11];
    const float* wgate    = (const float*)d_in[12];
    float* out = (float*)d_out;

    const int smem_cos  = (128 * PA + 128 * PB + 128) * 4;   // 138240
    const int smem_read = (64 * PB * 2) * 4;                 // 69632
    const int smem_mem  = (128 * PA + 128 * PB) * 4;         // 137216

    cudaFuncSetAttribute(k_cos,  cudaFuncAttributeMaxDynamicSharedMemorySize, smem_cos);
    cudaFuncSetAttribute(k_read, cudaFuncAttributeMaxDynamicSharedMemorySize, smem_read);
    cudaFuncSetAttribute(k_mem,  cudaFuncAttributeMaxDynamicSharedMemorySize, smem_mem);

    k_init<<<128, 256>>>(out + OFF_READ);
    k_lstm<<<dim3(8, 16), 256>>>(inputs, r_tm1, h_tm1, c_tm1, Wk, Wr, bias, out);
    k_knorm<<<32, 256>>>();
    k_cos<<<dim3(2, 256), 256, smem_cos>>>(m_tm1);
    k_soft<<<256, 256>>>(c_wr_tm1, c_wlu_tm1, c_wu_tm1, wgate, out);
    k_argmin<<<1, 256>>>();
    k_read<<<dim3(2, 32), 256, smem_read>>>(m_tm1, out + OFF_CWR, out + OFF_READ);
    k_mem<<<256, 256, smem_mem>>>(m_tm1, out + OFF_CWW, out + OFF_MEMORY);
    k_wlu<<<2048, 256>>>(out + OFF_CWU, out + OFF_CWLU);
}

// round 6
// speedup vs baseline: 1.2124x; 1.1340x over previous
#include <cuda_runtime.h>
#include <math.h>
#include <stdint.h>

#define MEMN 32768
#define BATCH 256
#define UNITS 128
#define IN_DIM 512

#define OFF_READ    0
#define OFF_MEMORY  (OFF_READ + BATCH*UNITS)
#define OFF_CWU     (OFF_MEMORY + MEMN*UNITS)
#define OFF_CWLU    (OFF_CWU + MEMN*BATCH)
#define OFF_CWR     (OFF_CWLU + MEMN*BATCH)
#define OFF_CWW     (OFF_CWR + MEMN*BATCH)
#define OFF_H       (OFF_CWW + MEMN*BATCH)
#define OFF_C       (OFF_H + BATCH*UNITS)

#define PA 132
#define PB 136

typedef unsigned long long ull;

// scratch (device globals: no allocation allowed)
__device__ float g_h[BATCH*UNITS];
__device__ float g_hT[UNITS*BATCH];          // [unit][batch]
__device__ float g_kinv[BATCH];
__device__ float g_cos[MEMN*BATCH];          // 32MB scratch (minv pre-applied)
__device__ ull   g_part[256*256];
__device__ float g_colmin[BATCH];
__device__ int   g_cnt[MEMN];

__device__ __forceinline__ unsigned ordf(float f) {
    unsigned u = __float_as_uint(f);
    return (u & 0x80000000u) ? ~u : (u | 0x80000000u);
}

__device__ __forceinline__ void mma_tf32(float* d, const unsigned* a, const unsigned* b) {
    asm volatile(
        "mma.sync.aligned.m16n8k8.row.col.f32.tf32.tf32.f32 "
        "{%0,%1,%2,%3}, {%4,%5,%6,%7}, {%8,%9}, {%0,%1,%2,%3};"
        : "+f"(d[0]), "+f"(d[1]), "+f"(d[2]), "+f"(d[3])
        : "r"(a[0]), "r"(a[1]), "r"(a[2]), "r"(a[3]), "r"(b[0]), "r"(b[1]));
}

__device__ __forceinline__ void split_tf32(float a, unsigned& hi, unsigned& lo) {
    unsigned u = __float_as_uint(a) & 0xffffe000u;   // exact tf32 (trunc)
    hi = u;
    lo = __float_as_uint(a - __uint_as_float(u));    // residual, exact in fp32
}

// ---------------- init ----------------
__global__ void k_init(float* __restrict__ out_read) {
    int i = blockIdx.x * 256 + threadIdx.x;
    if (i < MEMN) g_cnt[i] = 0;
    if (i < BATCH*UNITS) out_read[i] = 0.f;
}

// ---------------- LSTM cell ----------------
__global__ void k_lstm(const float* __restrict__ inputs, const float* __restrict__ r_tm1,
                       const float* __restrict__ h_tm1, const float* __restrict__ c_tm1,
                       const float* __restrict__ Wk, const float* __restrict__ Wr,
                       const float* __restrict__ bias, float* __restrict__ out) {
    __shared__ float sA[16][128];
    __shared__ float sB[128][64];
    int t = threadIdx.x;
    int utile = blockIdx.x, btile = blockIdx.y;
    int ul = t & 15, bl = t >> 4;
    float acc[4] = {0.f, 0.f, 0.f, 0.f};

    for (int kc = 0; kc < 6; kc++) {
        #pragma unroll
        for (int p = 0; p < 2; p++) {
            int i = t + p * 256;
            int row = i >> 5, c4 = (i & 31) * 4;
            int b = btile * 16 + row;
            const float* src;
            if (kc < 4)       src = inputs + b * IN_DIM + kc * 128 + c4;
            else if (kc == 4) src = r_tm1 + b * UNITS + c4;
            else              src = h_tm1 + b * UNITS + c4;
            *(float4*)&sA[row][c4] = *(const float4*)src;
        }
        #pragma unroll
        for (int p = 0; p < 8; p++) {
            int i = t + p * 256;
            int k = i >> 4, c4 = (i & 15) * 4;
            int q = c4 >> 4, jr = c4 & 15;
            int jc = utile * 16 + jr + q * 128;
            float4 v;
            if (kc < 5) v = *(const float4*)(Wk + (kc * 128 + k) * 512 + jc);
            else        v = *(const float4*)(Wr + k * 512 + jc);
            *(float4*)&sB[k][c4] = v;
        }
        __syncthreads();
        #pragma unroll 8
        for (int k = 0; k < 128; k++) {
            float a = sA[bl][k];
            acc[0] += a * sB[k][ul];
            acc[1] += a * sB[k][16 + ul];
            acc[2] += a * sB[k][32 + ul];
            acc[3] += a * sB[k][48 + ul];
        }
        __syncthreads();
    }
    int b = btile * 16 + bl, u = utile * 16 + ul;
    float zi = acc[0] + bias[u];
    float zf = acc[1] + bias[128 + u];
    float zg = acc[2] + bias[256 + u];
    float zo = acc[3] + bias[384 + u];
    float si = 1.f / (1.f + expf(-zi));
    float sf = 1.f / (1.f + expf(-zf));
    float so = 1.f / (1.f + expf(-zo));
    float cn = sf * c_tm1[b * UNITS + u] + si * tanhf(zg);
    float hn = so * tanhf(cn);
    out[OFF_H + b * UNITS + u] = hn;
    out[OFF_C + b * UNITS + u] = cn;
    g_h[b * UNITS + u] = hn;
}

// ---------------- key inverse norms + h transpose ----------------
__global__ void k_knorm() {
    int t = threadIdx.x, w = t >> 5, l = t & 31;
    int b = blockIdx.x * 8 + w;
    float s = 0.f;
    #pragma unroll
    for (int i = 0; i < 4; i++) { float v = g_h[b * UNITS + l + 32 * i]; s += v * v; }
    #pragma unroll
    for (int o = 16; o; o >>= 1) s += __shfl_xor_sync(0xffffffffu, s, o);
    if (l == 0) g_kinv[b] = rsqrtf(fmaxf(s, 1e-12f));
    #pragma unroll
    for (int p = 0; p < 4; p++) {
        int idx = blockIdx.x * 1024 + p * 256 + t;
        g_hT[(idx & 127) * BATCH + (idx >> 7)] = g_h[idx];
    }
}

// ---------------- cosine GEMM, tf32 3-split, 512 thr ----------------------
// grid (2 ntiles, 256 mtiles). CTA 128m x 128n, 16 warps, warp tile 32x32.
__global__ void __launch_bounds__(512) k_cos(const float* __restrict__ mptr) {
    extern __shared__ float sm[];
    float* sA = sm;                      // [128][PA]
    float* sB = sm + 128 * PA;           // [128][PB]
    float* sSS = sB + 128 * PB;          // [128] minv

    int t = threadIdx.x;
    int lane = t & 31, wid = t >> 5;
    int qr = lane >> 2, qc = lane & 3;
    int nbase = blockIdx.x * 128, mbase = blockIdx.y * 128;

    #pragma unroll
    for (int i = 0; i < 8; i++) {
        int g = t + i * 512;
        int r = g >> 5, c4 = (g & 31) << 2;
        *(float4*)&sA[r * PA + c4] = *(const float4*)(mptr + (mbase + r) * UNITS + c4);
        *(float4*)&sB[r * PB + c4] = *(const float4*)(g_hT + r * BATCH + nbase + c4);
    }
    __syncthreads();
    if (t < 128) {
        float ss = 0.f;
        #pragma unroll
        for (int i = 0; i < 32; i++) {
            float4 v = *(float4*)&sA[t * PA + i * 4];
            ss += v.x * v.x + v.y * v.y + v.z * v.z + v.w * v.w;
        }
        sSS[t] = rsqrtf(fmaxf(ss, 1e-12f));
    }
    __syncthreads();

    int wm = (wid >> 2) * 32, wn = (wid & 3) * 32;
    float acc[2][4][4];
    #pragma unroll
    for (int i = 0; i < 2; i++)
        #pragma unroll
        for (int j = 0; j < 4; j++)
            #pragma unroll
            for (int q = 0; q < 4; q++) acc[i][j][q] = 0.f;

    for (int ks = 0; ks < 16; ks++) {
        int kb = ks * 8;
        unsigned ah[2][4], al[2][4], bh[4][2], bl[4][2];
        #pragma unroll
        for (int mt = 0; mt < 2; mt++) {
            int rb = wm + mt * 16;
            split_tf32(sA[(rb + qr) * PA + kb + qc],         ah[mt][0], al[mt][0]);
            split_tf32(sA[(rb + 8 + qr) * PA + kb + qc],     ah[mt][1], al[mt][1]);
            split_tf32(sA[(rb + qr) * PA + kb + 4 + qc],     ah[mt][2], al[mt][2]);
            split_tf32(sA[(rb + 8 + qr) * PA + kb + 4 + qc], ah[mt][3], al[mt][3]);
        }
        #pragma unroll
        for (int nt = 0; nt < 4; nt++) {
            int cb = wn + nt * 8;
            split_tf32(sB[(kb + qc) * PB + cb + qr],     bh[nt][0], bl[nt][0]);
            split_tf32(sB[(kb + 4 + qc) * PB + cb + qr], bh[nt][1], bl[nt][1]);
        }
        #pragma unroll
        for (int mt = 0; mt < 2; mt++)
            #pragma unroll
            for (int nt = 0; nt < 4; nt++) {
                mma_tf32(acc[mt][nt], ah[mt], bh[nt]);
                mma_tf32(acc[mt][nt], al[mt], bh[nt]);
                mma_tf32(acc[mt][nt], ah[mt], bl[nt]);
            }
    }

    #pragma unroll
    for (int mt = 0; mt < 2; mt++) {
        int r0 = wm + mt * 16 + qr;
        float s0 = sSS[r0], s1 = sSS[r0 + 8];
        #pragma unroll
        for (int nt = 0; nt < 4; nt++) {
            int c = wn + nt * 8 + 2 * qc;
            float2 o0 = make_float2(acc[mt][nt][0] * s0, acc[mt][nt][1] * s0);
            float2 o1 = make_float2(acc[mt][nt][2] * s1, acc[mt][nt][3] * s1);
            *(float2*)&g_cos[(mbase + r0) * BATCH + nbase + c] = o0;
            *(float2*)&g_cos[(mbase + r0 + 8) * BATCH + nbase + c] = o1;
        }
    }
}

// ---------------- softmax + c_ww + c_wu + per-column min partials ----------
__global__ void k_soft(const float* __restrict__ wr_tm1, const float* __restrict__ wlu_tm1,
                       const float* __restrict__ wu_tm1, const float* __restrict__ wgate,
                       float* __restrict__ out) {
    __shared__ ull s_enc[8][256];
    __shared__ float sKinv[256];
    int t = threadIdx.x, w = t >> 5, l = t & 31;
    sKinv[t] = g_kinv[t];
    __syncthreads();
    float wg = 1.f / (1.f + __expf(-wgate[0]));
    float omw = 1.f - wg;
    ull emin[8];
    #pragma unroll
    for (int j = 0; j < 8; j++) emin[j] = 0xFFFFFFFFFFFFFFFFull;

    for (int i = 0; i < 16; i++) {
        int r = blockIdx.x * 128 + w * 16 + i;
        float x[8];
        #pragma unroll
        for (int j = 0; j < 8; j++) x[j] = g_cos[r * BATCH + l + 32 * j] * sKinv[l + 32 * j];
        float mx = x[0];
        #pragma unroll
        for (int j = 1; j < 8; j++) mx = fmaxf(mx, x[j]);
        #pragma unroll
        for (int o = 16; o; o >>= 1) mx = fmaxf(mx, __shfl_xor_sync(0xffffffffu, mx, o));
        float e[8], s = 0.f;
        #pragma unroll
        for (int j = 0; j < 8; j++) { e[j] = __expf(x[j] - mx); s += e[j]; }
        #pragma unroll
        for (int o = 16; o; o >>= 1) s += __shfl_xor_sync(0xffffffffu, s, o);
        float inv = 1.f / s;
        #pragma unroll
        for (int j = 0; j < 8; j++) {
            int c = l + 32 * j;
            int idx = r * BATCH + c;
            float wr = e[j] * inv;
            float ww = wg * wr_tm1[idx] + omw + wlu_tm1[idx];
            float wu = 0.95f * wu_tm1[idx] + wr + ww;
            out[OFF_CWR + idx] = wr;
            out[OFF_CWW + idx] = ww;
            out[OFF_CWU + idx] = wu;
            ull enc = ((ull)ordf(wu) << 32)
                    | (ull)(0xFFFFFFFFu - (unsigned)r);
            emin[j] = (enc < emin[j]) ? enc : emin[j];
        }
    }
    #pragma unroll
    for (int j = 0; j < 8; j++) s_enc[w][l + 32 * j] = emin[j];
    __syncthreads();
    ull e = s_enc[0][t];
    #pragma unroll
    for (int w2 = 1; w2 < 8; w2++) { ull v = s_enc[w2][t]; e = (v < e) ? v : e; }
    g_part[blockIdx.x * 256 + t] = e;
}

// ---------------- argmin finalize ---------------- 1 x 256
__global__ void k_argmin() {
    int c = threadIdx.x;
    ull e = 0xFFFFFFFFFFFFFFFFull;
    for (int i = 0; i < 256; i++) {
        ull v = g_part[i * 256 + c];
        e = (v < e) ? v : e;
    }
    unsigned hi = (unsigned)(e >> 32);
    unsigned bits = (hi & 0x80000000u) ? (hi & 0x7FFFFFFFu) : ~hi;
    g_colmin[c] = __uint_as_float(bits);
    int idx = (int)(0xFFFFFFFFu - (unsigned)(e & 0xFFFFFFFFull));
    atomicAdd(&g_cnt[idx], 1);
}

// ---------------- read = c_wr.T @ m_tm1, tf32 3-split, 512 thr -------------
// grid (2 btiles, 64 kchunks of 512). CTA 128b x 128u, 16 warps, warp 32x32.
__global__ void __launch_bounds__(512) k_read(const float* __restrict__ mptr,
                                              const float* __restrict__ cwr,
                                              float* __restrict__ out_read) {
    extern __shared__ float sm[];
    float* sW = sm;                  // [64][PB]  wr chunk [k][b]
    float* sM = sm + 64 * PB;        // [64][PB]  m chunk [k][u]

    int t = threadIdx.x;
    int lane = t & 31, wid = t >> 5;
    int qr = lane >> 2, qc = lane & 3;
    int bbase = blockIdx.x * 128;
    int kchunk = blockIdx.y;
    int wm = (wid >> 2) * 32, wn = (wid & 3) * 32;

    float acc[2][4][4];
    #pragma unroll
    for (int i = 0; i < 2; i++)
        #pragma unroll
        for (int j = 0; j < 4; j++)
            #pragma unroll
            for (int q = 0; q < 4; q++) acc[i][j][q] = 0.f;

    for (int it = 0; it < 8; it++) {
        int kb0 = kchunk * 512 + it * 64;
        #pragma unroll
        for (int i = 0; i < 4; i++) {
            int g = t + i * 512;
            int r = g >> 5, c4 = (g & 31) << 2;
            *(float4*)&sW[r * PB + c4] = *(const float4*)(cwr + (kb0 + r) * BATCH + bbase + c4);
            *(float4*)&sM[r * PB + c4] = *(const float4*)(mptr + (kb0 + r) * UNITS + c4);
        }
        __syncthreads();
        #pragma unroll
        for (int ks = 0; ks < 8; ks++) {
            int kb = ks * 8;
            unsigned ah[2][4], al[2][4], bh[4][2], bl[4][2];
            #pragma unroll
            for (int mt = 0; mt < 2; mt++) {
                int rb = wm + mt * 16;
                split_tf32(sW[(kb + qc) * PB + rb + qr],         ah[mt][0], al[mt][0]);
                split_tf32(sW[(kb + qc) * PB + rb + 8 + qr],     ah[mt][1], al[mt][1]);
                split_tf32(sW[(kb + 4 + qc) * PB + rb + qr],     ah[mt][2], al[mt][2]);
                split_tf32(sW[(kb + 4 + qc) * PB + rb + 8 + qr], ah[mt][3], al[mt][3]);
            }
            #pragma unroll
            for (int nt = 0; nt < 4; nt++) {
                int cb = wn + nt * 8;
                split_tf32(sM[(kb + qc) * PB + cb + qr],     bh[nt][0], bl[nt][0]);
                split_tf32(sM[(kb + 4 + qc) * PB + cb + qr], bh[nt][1], bl[nt][1]);
            }
            #pragma unroll
            for (int mt = 0; mt < 2; mt++)
                #pragma unroll
                for (int nt = 0; nt < 4; nt++) {
                    mma_tf32(acc[mt][nt], ah[mt], bh[nt]);
                    mma_tf32(acc[mt][nt], al[mt], bh[nt]);
                    mma_tf32(acc[mt][nt], ah[mt], bl[nt]);
                }
        }
        __syncthreads();
    }
    #pragma unroll
    for (int mt = 0; mt < 2; mt++) {
        int r0 = bbase + wm + mt * 16 + qr;
        #pragma unroll
        for (int nt = 0; nt < 4; nt++) {
            int c = wn + nt * 8 + 2 * qc;
            atomicAdd(&out_read[r0 * UNITS + c],           acc[mt][nt][0]);
            atomicAdd(&out_read[r0 * UNITS + c + 1],       acc[mt][nt][1]);
            atomicAdd(&out_read[(r0 + 8) * UNITS + c],     acc[mt][nt][2]);
            atomicAdd(&out_read[(r0 + 8) * UNITS + c + 1], acc[mt][nt][3]);
        }
    }
}

// ---------------- memory = c_ww @ h + (256 - cnt[m]) * m_tm1, 512 thr ------
// grid 256 mtiles. CTA 128m x 128u, K=256 in 2 halves, 16 warps, warp 32x32.
__global__ void __launch_bounds__(512) k_mem(const float* __restrict__ mptr,
                                             const float* __restrict__ cww,
                                             float* __restrict__ out_mem) {
    extern __shared__ float sm[];
    float* sA = sm;                  // [128][PA]  cww half [row][k]
    float* sB = sm + 128 * PA;       // [128][PB]  h half [k=b][u]

    int t = threadIdx.x;
    int lane = t & 31, wid = t >> 5;
    int qr = lane >> 2, qc = lane & 3;
    int mbase = blockIdx.x * 128;
    int wm = (wid >> 2) * 32, wn = (wid & 3) * 32;

    float acc[2][4][4];
    #pragma unroll
    for (int i = 0; i < 2; i++)
        #pragma unroll
        for (int j = 0; j < 4; j++)
            #pragma unroll
            for (int q = 0; q < 4; q++) acc[i][j][q] = 0.f;

    for (int kc = 0; kc < 2; kc++) {
        #pragma unroll
        for (int i = 0; i < 8; i++) {
            int g = t + i * 512;
            int r = g >> 5, c4 = (g & 31) << 2;
            *(float4*)&sA[r * PA + c4] = *(const float4*)(cww + (mbase + r) * BATCH + kc * 128 + c4);
            *(float4*)&sB[r * PB + c4] = *(const float4*)(g_h + (kc * 128 + r) * UNITS + c4);
        }
        __syncthreads();
        #pragma unroll
        for (int ks = 0; ks < 16; ks++) {
            int kb = ks * 8;
            unsigned ah[2][4], al[2][4], bh[4][2], bl[4][2];
            #pragma unroll
            for (int mt = 0; mt < 2; mt++) {
                int rb = wm + mt * 16;
                split_tf32(sA[(rb + qr) * PA + kb + qc],         ah[mt][0], al[mt][0]);
                split_tf32(sA[(rb + 8 + qr) * PA + kb + qc],     ah[mt][1], al[mt][1]);
                split_tf32(sA[(rb + qr) * PA + kb + 4 + qc],     ah[mt][2], al[mt][2]);
                split_tf32(sA[(rb + 8 + qr) * PA + kb + 4 + qc], ah[mt][3], al[mt][3]);
            }
            #pragma unroll
            for (int nt = 0; nt < 4; nt++) {
                int cb = wn + nt * 8;
                split_tf32(sB[(kb + qc) * PB + cb + qr],     bh[nt][0], bl[nt][0]);
                split_tf32(sB[(kb + 4 + qc) * PB + cb + qr], bh[nt][1], bl[nt][1]);
            }
            #pragma unroll
            for (int mt = 0; mt < 2; mt++)
                #pragma unroll
                for (int nt = 0; nt < 4; nt++) {
                    mma_tf32(acc[mt][nt], ah[mt], bh[nt]);
                    mma_tf32(acc[mt][nt], al[mt], bh[nt]);
                    mma_tf32(acc[mt][nt], ah[mt], bl[nt]);
                }
        }
        __syncthreads();
    }

    #pragma unroll
    for (int mt = 0; mt < 2; mt++) {
        int r0 = mbase + wm + mt * 16 + qr;
        float f0 = (float)(BATCH - g_cnt[r0]);
        float f1 = (float)(BATCH - g_cnt[r0 + 8]);
        #pragma unroll
        for (int nt = 0; nt < 4; nt++) {
            int c = wn + nt * 8 + 2 * qc;
            float2 m0 = *(const float2*)(mptr + r0 * UNITS + c);
            float2 m1 = *(const float2*)(mptr + (r0 + 8) * UNITS + c);
            float2 o0 = make_float2(acc[mt][nt][0] + f0 * m0.x, acc[mt][nt][1] + f0 * m0.y);
            float2 o1 = make_float2(acc[mt][nt][2] + f1 * m1.x, acc[mt][nt][3] + f1 * m1.y);
            *(float2*)(out_mem + r0 * UNITS + c) = o0;
            *(float2*)(out_mem + (r0 + 8) * UNITS + c) = o1;
        }
    }
}

// ---------------- c_wlu = (c_wu <= colmin) ----------------
__global__ void k_wlu(const float* __restrict__ out_cwu, float* __restrict__ out_cwlu) {
    __shared__ float smin[256];
    smin[threadIdx.x] = g_colmin[threadIdx.x];
    __syncthreads();
    const int total = MEMN * BATCH / 4;
    for (int i4 = blockIdx.x * 256 + threadIdx.x; i4 < total; i4 += gridDim.x * 256) {
        float4 v = *(const float4*)(out_cwu + i4 * 4);
        int c = (i4 & 63) * 4;
        float4 o;
        o.x = (v.x <= smin[c])     ? 1.f : 0.f;
        o.y = (v.y <= smin[c + 1]) ? 1.f : 0.f;
        o.z = (v.z <= smin[c + 2]) ? 1.f : 0.f;
        o.w = (v.w <= smin[c + 3]) ? 1.f : 0.f;
        *(float4*)(out_cwlu + i4 * 4) = o;
    }
}

extern "C" void kernel_launch(void* const* d_in, const int* in_sizes, int n_in,
                              void* d_out, int out_size) {
    (void)in_sizes; (void)n_in; (void)out_size;
    const float* inputs   = (const float*)d_in[0];
    const float* r_tm1    = (const float*)d_in[1];
    const float* m_tm1    = (const float*)d_in[2];
    const float* c_wu_tm1 = (const float*)d_in[3];
    const float* c_wlu_tm1= (const float*)d_in[4];
    const float* c_wr_tm1 = (const float*)d_in[5];
    const float* h_tm1    = (const float*)d_in[7];
    const float* c_tm1    = (const float*)d_in[8];
    const float* Wk       = (const float*)d_in[9];
    const float* Wr       = (const float*)d_in[10];
    const float* bias     = (const float*)d_in[11];
    const float* wgate    = (const float*)d_in[12];
    float* out = (float*)d_out;

    const int smem_cos  = (128 * PA + 128 * PB + 128) * 4;   // 138240
    const int smem_read = (64 * PB * 2) * 4;                 // 69632
    const int smem_mem  = (128 * PA + 128 * PB) * 4;         // 137216

    cudaFuncSetAttribute(k_cos,  cudaFuncAttributeMaxDynamicSharedMemorySize, smem_cos);
    cudaFuncSetAttribute(k_read, cudaFuncAttributeMaxDynamicSharedMemorySize, smem_read);
    cudaFuncSetAttribute(k_mem,  cudaFuncAttributeMaxDynamicSharedMemorySize, smem_mem);

    k_init<<<128, 256>>>(out + OFF_READ);
    k_lstm<<<dim3(8, 16), 256>>>(inputs, r_tm1, h_tm1, c_tm1, Wk, Wr, bias, out);
    k_knorm<<<32, 256>>>();
    k_cos<<<dim3(2, 256), 512, smem_cos>>>(m_tm1);
    k_soft<<<256, 256>>>(c_wr_tm1, c_wlu_tm1, c_wu_tm1, wgate, out);
    k_argmin<<<1, 256>>>();
    k_read<<<dim3(2, 64), 512, smem_read>>>(m_tm1, out + OFF_CWR, out + OFF_READ);
    k_mem<<<256, 512, smem_mem>>>(m_tm1, out + OFF_CWW, out + OFF_MEMORY);
    k_wlu<<<2048, 256>>>(out + OFF_CWU, out + OFF_CWLU);
}

// round 7
// speedup vs baseline: 1.3251x; 1.0929x over previous
#include <cuda_runtime.h>
#include <math.h>
#include <stdint.h>

#define MEMN 32768
#define BATCH 256
#define UNITS 128
#define IN_DIM 512

#define OFF_READ    0
#define OFF_MEMORY  (OFF_READ + BATCH*UNITS)
#define OFF_CWU     (OFF_MEMORY + MEMN*UNITS)
#define OFF_CWLU    (OFF_CWU + MEMN*BATCH)
#define OFF_CWR     (OFF_CWLU + MEMN*BATCH)
#define OFF_CWW     (OFF_CWR + MEMN*BATCH)
#define OFF_H       (OFF_CWW + MEMN*BATCH)
#define OFF_C       (OFF_H + BATCH*UNITS)

#define PA 132
#define PB 136

typedef unsigned long long ull;

// scratch (device globals: no allocation allowed)
__device__ float g_h[BATCH*UNITS];
__device__ float g_hT[UNITS*BATCH];          // [unit][batch]
__device__ float g_kinv[BATCH];
__device__ float g_cos[MEMN*BATCH];          // 32MB scratch (minv pre-applied)
__device__ ull   g_part[256*256];
__device__ float g_colmin[BATCH];
__device__ int   g_cnt[MEMN];

__device__ __forceinline__ unsigned ordf(float f) {
    unsigned u = __float_as_uint(f);
    return (u & 0x80000000u) ? ~u : (u | 0x80000000u);
}

__device__ __forceinline__ void mma_tf32(float* d, const unsigned* a, const unsigned* b) {
    asm volatile(
        "mma.sync.aligned.m16n8k8.row.col.f32.tf32.tf32.f32 "
        "{%0,%1,%2,%3}, {%4,%5,%6,%7}, {%8,%9}, {%0,%1,%2,%3};"
        : "+f"(d[0]), "+f"(d[1]), "+f"(d[2]), "+f"(d[3])
        : "r"(a[0]), "r"(a[1]), "r"(a[2]), "r"(a[3]), "r"(b[0]), "r"(b[1]));
}

// round-to-nearest tf32 of b (single operand; error ~6e-5 rel)
__device__ __forceinline__ unsigned rna_tf32(float a) {
    unsigned r;
    asm("cvt.rna.tf32.f32 %0, %1;" : "=r"(r) : "f"(a));
    return r;
}
// exact split: a = hi + lo, hi = rna_tf32(a), lo exact in fp32
__device__ __forceinline__ void split2(float a, unsigned& hi, unsigned& lo) {
    unsigned h;
    asm("cvt.rna.tf32.f32 %0, %1;" : "=r"(h) : "f"(a));
    hi = h;
    lo = __float_as_uint(a - __uint_as_float(h));
}

// ---------------- init ----------------
__global__ void k_init(float* __restrict__ out_read) {
    int i = blockIdx.x * 256 + threadIdx.x;
    if (i < MEMN) g_cnt[i] = 0;
    if (i < BATCH*UNITS) out_read[i] = 0.f;
}

// ---------------- LSTM cell ----------------
__global__ void k_lstm(const float* __restrict__ inputs, const float* __restrict__ r_tm1,
                       const float* __restrict__ h_tm1, const float* __restrict__ c_tm1,
                       const float* __restrict__ Wk, const float* __restrict__ Wr,
                       const float* __restrict__ bias, float* __restrict__ out) {
    __shared__ float sA[16][128];
    __shared__ float sB[128][64];
    int t = threadIdx.x;
    int utile = blockIdx.x, btile = blockIdx.y;
    int ul = t & 15, bl = t >> 4;
    float acc[4] = {0.f, 0.f, 0.f, 0.f};

    for (int kc = 0; kc < 6; kc++) {
        #pragma unroll
        for (int p = 0; p < 2; p++) {
            int i = t + p * 256;
            int row = i >> 5, c4 = (i & 31) * 4;
            int b = btile * 16 + row;
            const float* src;
            if (kc < 4)       src = inputs + b * IN_DIM + kc * 128 + c4;
            else if (kc == 4) src = r_tm1 + b * UNITS + c4;
            else              src = h_tm1 + b * UNITS + c4;
            *(float4*)&sA[row][c4] = *(const float4*)src;
        }
        #pragma unroll
        for (int p = 0; p < 8; p++) {
            int i = t + p * 256;
            int k = i >> 4, c4 = (i & 15) * 4;
            int q = c4 >> 4, jr = c4 & 15;
            int jc = utile * 16 + jr + q * 128;
            float4 v;
            if (kc < 5) v = *(const float4*)(Wk + (kc * 128 + k) * 512 + jc);
            else        v = *(const float4*)(Wr + k * 512 + jc);
            *(float4*)&sB[k][c4] = v;
        }
        __syncthreads();
        #pragma unroll 8
        for (int k = 0; k < 128; k++) {
            float a = sA[bl][k];
            acc[0] += a * sB[k][ul];
            acc[1] += a * sB[k][16 + ul];
            acc[2] += a * sB[k][32 + ul];
            acc[3] += a * sB[k][48 + ul];
        }
        __syncthreads();
    }
    int b = btile * 16 + bl, u = utile * 16 + ul;
    float zi = acc[0] + bias[u];
    float zf = acc[1] + bias[128 + u];
    float zg = acc[2] + bias[256 + u];
    float zo = acc[3] + bias[384 + u];
    float si = 1.f / (1.f + expf(-zi));
    float sf = 1.f / (1.f + expf(-zf));
    float so = 1.f / (1.f + expf(-zo));
    float cn = sf * c_tm1[b * UNITS + u] + si * tanhf(zg);
    float hn = so * tanhf(cn);
    out[OFF_H + b * UNITS + u] = hn;
    out[OFF_C + b * UNITS + u] = cn;
    g_h[b * UNITS + u] = hn;
}

// ---------------- key inverse norms + h transpose ----------------
__global__ void k_knorm() {
    int t = threadIdx.x, w = t >> 5, l = t & 31;
    int b = blockIdx.x * 8 + w;
    float s = 0.f;
    #pragma unroll
    for (int i = 0; i < 4; i++) { float v = g_h[b * UNITS + l + 32 * i]; s += v * v; }
    #pragma unroll
    for (int o = 16; o; o >>= 1) s += __shfl_xor_sync(0xffffffffu, s, o);
    if (l == 0) g_kinv[b] = rsqrtf(fmaxf(s, 1e-12f));
    #pragma unroll
    for (int p = 0; p < 4; p++) {
        int idx = blockIdx.x * 1024 + p * 256 + t;
        g_hT[(idx & 127) * BATCH + (idx >> 7)] = g_h[idx];
    }
}

// ---------------- cosine GEMM, tf32 2-MMA split, 2 CTAs/SM -----------------
// grid (2 ntiles, 512 mtiles), 256 thr. CTA 64m x 128n, 8 warps, warp 32x32.
__global__ void __launch_bounds__(256) k_cos(const float* __restrict__ mptr) {
    extern __shared__ float sm[];
    float* sA = sm;                      // [64][PA]
    float* sB = sm + 64 * PA;            // [128][PB]
    float* sSS = sB + 128 * PB;          // [64] minv

    int t = threadIdx.x;
    int lane = t & 31, wid = t >> 5;
    int qr = lane >> 2, qc = lane & 3;
    int nbase = blockIdx.x * 128, mbase = blockIdx.y * 64;

    #pragma unroll
    for (int i = 0; i < 8; i++) {
        int g = t + i * 256;
        int r = g >> 5, c4 = (g & 31) << 2;
        *(float4*)&sA[r * PA + c4] = *(const float4*)(mptr + (mbase + r) * UNITS + c4);
    }
    #pragma unroll
    for (int i = 0; i < 16; i++) {
        int g = t + i * 256;
        int r = g >> 5, c4 = (g & 31) << 2;
        *(float4*)&sB[r * PB + c4] = *(const float4*)(g_hT + r * BATCH + nbase + c4);
    }
    __syncthreads();
    if (t < 64) {
        float ss = 0.f;
        #pragma unroll
        for (int i = 0; i < 32; i++) {
            float4 v = *(float4*)&sA[t * PA + i * 4];
            ss += v.x * v.x + v.y * v.y + v.z * v.z + v.w * v.w;
        }
        sSS[t] = rsqrtf(fmaxf(ss, 1e-12f));
    }
    __syncthreads();

    int wm = (wid >> 2) * 32, wn = (wid & 3) * 32;
    float acc[2][4][4];
    #pragma unroll
    for (int i = 0; i < 2; i++)
        #pragma unroll
        for (int j = 0; j < 4; j++)
            #pragma unroll
            for (int q = 0; q < 4; q++) acc[i][j][q] = 0.f;

    for (int ks = 0; ks < 16; ks++) {
        int kb = ks * 8;
        unsigned ah[2][4], al[2][4], bb[4][2];
        #pragma unroll
        for (int mt = 0; mt < 2; mt++) {
            int rb = wm + mt * 16;
            split2(sA[(rb + qr) * PA + kb + qc],         ah[mt][0], al[mt][0]);
            split2(sA[(rb + 8 + qr) * PA + kb + qc],     ah[mt][1], al[mt][1]);
            split2(sA[(rb + qr) * PA + kb + 4 + qc],     ah[mt][2], al[mt][2]);
            split2(sA[(rb + 8 + qr) * PA + kb + 4 + qc], ah[mt][3], al[mt][3]);
        }
        #pragma unroll
        for (int nt = 0; nt < 4; nt++) {
            int cb = wn + nt * 8;
            bb[nt][0] = rna_tf32(sB[(kb + qc) * PB + cb + qr]);
            bb[nt][1] = rna_tf32(sB[(kb + 4 + qc) * PB + cb + qr]);
        }
        #pragma unroll
        for (int mt = 0; mt < 2; mt++)
            #pragma unroll
            for (int nt = 0; nt < 4; nt++) {
                mma_tf32(acc[mt][nt], ah[mt], bb[nt]);
                mma_tf32(acc[mt][nt], al[mt], bb[nt]);
            }
    }

    #pragma unroll
    for (int mt = 0; mt < 2; mt++) {
        int r0 = wm + mt * 16 + qr;
        float s0 = sSS[r0], s1 = sSS[r0 + 8];
        #pragma unroll
        for (int nt = 0; nt < 4; nt++) {
            int c = wn + nt * 8 + 2 * qc;
            float2 o0 = make_float2(acc[mt][nt][0] * s0, acc[mt][nt][1] * s0);
            float2 o1 = make_float2(acc[mt][nt][2] * s1, acc[mt][nt][3] * s1);
            *(float2*)&g_cos[(mbase + r0) * BATCH + nbase + c] = o0;
            *(float2*)&g_cos[(mbase + r0 + 8) * BATCH + nbase + c] = o1;
        }
    }
}

// ---------------- softmax + c_ww + c_wu + per-column min partials ----------
__global__ void k_soft(const float* __restrict__ wr_tm1, const float* __restrict__ wlu_tm1,
                       const float* __restrict__ wu_tm1, const float* __restrict__ wgate,
                       float* __restrict__ out) {
    __shared__ ull s_enc[8][256];
    __shared__ float sKinv[256];
    int t = threadIdx.x, w = t >> 5, l = t & 31;
    sKinv[t] = g_kinv[t];
    __syncthreads();
    float wg = 1.f / (1.f + __expf(-wgate[0]));
    float omw = 1.f - wg;
    ull emin[8];
    #pragma unroll
    for (int j = 0; j < 8; j++) emin[j] = 0xFFFFFFFFFFFFFFFFull;

    for (int i = 0; i < 16; i++) {
        int r = blockIdx.x * 128 + w * 16 + i;
        float x[8];
        #pragma unroll
        for (int j = 0; j < 8; j++) x[j] = g_cos[r * BATCH + l + 32 * j] * sKinv[l + 32 * j];
        float mx = x[0];
        #pragma unroll
        for (int j = 1; j < 8; j++) mx = fmaxf(mx, x[j]);
        #pragma unroll
        for (int o = 16; o; o >>= 1) mx = fmaxf(mx, __shfl_xor_sync(0xffffffffu, mx, o));
        float e[8], s = 0.f;
        #pragma unroll
        for (int j = 0; j < 8; j++) { e[j] = __expf(x[j] - mx); s += e[j]; }
        #pragma unroll
        for (int o = 16; o; o >>= 1) s += __shfl_xor_sync(0xffffffffu, s, o);
        float inv = 1.f / s;
        #pragma unroll
        for (int j = 0; j < 8; j++) {
            int c = l + 32 * j;
            int idx = r * BATCH + c;
            float wr = e[j] * inv;
            float ww = wg * wr_tm1[idx] + omw + wlu_tm1[idx];
            float wu = 0.95f * wu_tm1[idx] + wr + ww;
            out[OFF_CWR + idx] = wr;
            out[OFF_CWW + idx] = ww;
            out[OFF_CWU + idx] = wu;
            ull enc = ((ull)ordf(wu) << 32)
                    | (ull)(0xFFFFFFFFu - (unsigned)r);
            emin[j] = (enc < emin[j]) ? enc : emin[j];
        }
    }
    #pragma unroll
    for (int j = 0; j < 8; j++) s_enc[w][l + 32 * j] = emin[j];
    __syncthreads();
    ull e = s_enc[0][t];
    #pragma unroll
    for (int w2 = 1; w2 < 8; w2++) { ull v = s_enc[w2][t]; e = (v < e) ? v : e; }
    g_part[blockIdx.x * 256 + t] = e;
}

// ---------------- argmin finalize ---------------- 1 x 256
__global__ void k_argmin() {
    int c = threadIdx.x;
    ull e = 0xFFFFFFFFFFFFFFFFull;
    for (int i = 0; i < 256; i++) {
        ull v = g_part[i * 256 + c];
        e = (v < e) ? v : e;
    }
    unsigned hi = (unsigned)(e >> 32);
    unsigned bits = (hi & 0x80000000u) ? (hi & 0x7FFFFFFFu) : ~hi;
    g_colmin[c] = __uint_as_float(bits);
    int idx = (int)(0xFFFFFFFFu - (unsigned)(e & 0xFFFFFFFFull));
    atomicAdd(&g_cnt[idx], 1);
}

// ---------------- read = c_wr.T @ m_tm1, tf32 2-MMA split, split-K ---------
// grid (2 btiles, 64 kchunks of 512). CTA 128b x 128u, 16 warps, warp 32x32.
__global__ void __launch_bounds__(512) k_read(const float* __restrict__ mptr,
                                              const float* __restrict__ cwr,
                                              float* __restrict__ out_read) {
    extern __shared__ float sm[];
    float* sW = sm;                  // [64][PB]  wr chunk [k][b]
    float* sM = sm + 64 * PB;        // [64][PB]  m chunk [k][u]

    int t = threadIdx.x;
    int lane = t & 31, wid = t >> 5;
    int qr = lane >> 2, qc = lane & 3;
    int bbase = blockIdx.x * 128;
    int kchunk = blockIdx.y;
    int wm = (wid >> 2) * 32, wn = (wid & 3) * 32;

    float acc[2][4][4];
    #pragma unroll
    for (int i = 0; i < 2; i++)
        #pragma unroll
        for (int j = 0; j < 4; j++)
            #pragma unroll
            for (int q = 0; q < 4; q++) acc[i][j][q] = 0.f;

    for (int it = 0; it < 8; it++) {
        int kb0 = kchunk * 512 + it * 64;
        #pragma unroll
        for (int i = 0; i < 4; i++) {
            int g = t + i * 512;
            int r = g >> 5, c4 = (g & 31) << 2;
            *(float4*)&sW[r * PB + c4] = *(const float4*)(cwr + (kb0 + r) * BATCH + bbase + c4);
            *(float4*)&sM[r * PB + c4] = *(const float4*)(mptr + (kb0 + r) * UNITS + c4);
        }
        __syncthreads();
        #pragma unroll
        for (int ks = 0; ks < 8; ks++) {
            int kb = ks * 8;
            unsigned ah[2][4], al[2][4], bb[4][2];
            #pragma unroll
            for (int mt = 0; mt < 2; mt++) {
                int rb = wm + mt * 16;
                split2(sW[(kb + qc) * PB + rb + qr],         ah[mt][0], al[mt][0]);
                split2(sW[(kb + qc) * PB + rb + 8 + qr],     ah[mt][1], al[mt][1]);
                split2(sW[(kb + 4 + qc) * PB + rb + qr],     ah[mt][2], al[mt][2]);
                split2(sW[(kb + 4 + qc) * PB + rb + 8 + qr], ah[mt][3], al[mt][3]);
            }
            #pragma unroll
            for (int nt = 0; nt < 4; nt++) {
                int cb = wn + nt * 8;
                bb[nt][0] = rna_tf32(sM[(kb + qc) * PB + cb + qr]);
                bb[nt][1] = rna_tf32(sM[(kb + 4 + qc) * PB + cb + qr]);
            }
            #pragma unroll
            for (int mt = 0; mt < 2; mt++)
                #pragma unroll
                for (int nt = 0; nt < 4; nt++) {
                    mma_tf32(acc[mt][nt], ah[mt], bb[nt]);
                    mma_tf32(acc[mt][nt], al[mt], bb[nt]);
                }
        }
        __syncthreads();
    }
    #pragma unroll
    for (int mt = 0; mt < 2; mt++) {
        int r0 = bbase + wm + mt * 16 + qr;
        #pragma unroll
        for (int nt = 0; nt < 4; nt++) {
            int c = wn + nt * 8 + 2 * qc;
            atomicAdd(&out_read[r0 * UNITS + c],           acc[mt][nt][0]);
            atomicAdd(&out_read[r0 * UNITS + c + 1],       acc[mt][nt][1]);
            atomicAdd(&out_read[(r0 + 8) * UNITS + c],     acc[mt][nt][2]);
            atomicAdd(&out_read[(r0 + 8) * UNITS + c + 1], acc[mt][nt][3]);
        }
    }
}

// ---------------- memory = c_ww @ h + (256 - cnt[m]) * m_tm1 ---------------
// grid 512 mtiles, 256 thr. CTA 64m x 128u, K=256 in 2 halves, 2 CTAs/SM.
__global__ void __launch_bounds__(256) k_mem(const float* __restrict__ mptr,
                                             const float* __restrict__ cww,
                                             float* __restrict__ out_mem) {
    extern __shared__ float sm[];
    float* sA = sm;                  // [64][PA]   cww half [row][k]
    float* sB = sm + 64 * PA;        // [128][PB]  h half [k=b][u]

    int t = threadIdx.x;
    int lane = t & 31, wid = t >> 5;
    int qr = lane >> 2, qc = lane & 3;
    int mbase = blockIdx.x * 64;
    int wm = (wid >> 2) * 32, wn = (wid & 3) * 32;

    float acc[2][4][4];
    #pragma unroll
    for (int i = 0; i < 2; i++)
        #pragma unroll
        for (int j = 0; j < 4; j++)
            #pragma unroll
            for (int q = 0; q < 4; q++) acc[i][j][q] = 0.f;

    for (int kc = 0; kc < 2; kc++) {
        #pragma unroll
        for (int i = 0; i < 8; i++) {
            int g = t + i * 256;
            int r = g >> 5, c4 = (g & 31) << 2;
            *(float4*)&sA[r * PA + c4] = *(const float4*)(cww + (mbase + r) * BATCH + kc * 128 + c4);
        }
        #pragma unroll
        for (int i = 0; i < 16; i++) {
            int g = t + i * 256;
            int r = g >> 5, c4 = (g & 31) << 2;
            *(float4*)&sB[r * PB + c4] = *(const float4*)(g_h + (kc * 128 + r) * UNITS + c4);
        }
        __syncthreads();
        #pragma unroll
        for (int ks = 0; ks < 16; ks++) {
            int kb = ks * 8;
            unsigned ah[2][4], al[2][4], bb[4][2];
            #pragma unroll
            for (int mt = 0; mt < 2; mt++) {
                int rb = wm + mt * 16;
                split2(sA[(rb + qr) * PA + kb + qc],         ah[mt][0], al[mt][0]);
                split2(sA[(rb + 8 + qr) * PA + kb + qc],     ah[mt][1], al[mt][1]);
                split2(sA[(rb + qr) * PA + kb + 4 + qc],     ah[mt][2], al[mt][2]);
                split2(sA[(rb + 8 + qr) * PA + kb + 4 + qc], ah[mt][3], al[mt][3]);
            }
            #pragma unroll
            for (int nt = 0; nt < 4; nt++) {
                int cb = wn + nt * 8;
                bb[nt][0] = rna_tf32(sB[(kb + qc) * PB + cb + qr]);
                bb[nt][1] = rna_tf32(sB[(kb + 4 + qc) * PB + cb + qr]);
            }
            #pragma unroll
            for (int mt = 0; mt < 2; mt++)
                #pragma unroll
                for (int nt = 0; nt < 4; nt++) {
                    mma_tf32(acc[mt][nt], ah[mt], bb[nt]);
                    mma_tf32(acc[mt][nt], al[mt], bb[nt]);
                }
        }
        __syncthreads();
    }

    #pragma unroll
    for (int mt = 0; mt < 2; mt++) {
        int r0 = mbase + wm + mt * 16 + qr;
        float f0 = (float)(BATCH - g_cnt[r0]);
        float f1 = (float)(BATCH - g_cnt[r0 + 8]);
        #pragma unroll
        for (int nt = 0; nt < 4; nt++) {
            int c = wn + nt * 8 + 2 * qc;
            float2 m0 = *(const float2*)(mptr + r0 * UNITS + c);
            float2 m1 = *(const float2*)(mptr + (r0 + 8) * UNITS + c);
            float2 o0 = make_float2(acc[mt][nt][0] + f0 * m0.x, acc[mt][nt][1] + f0 * m0.y);
            float2 o1 = make_float2(acc[mt][nt][2] + f1 * m1.x, acc[mt][nt][3] + f1 * m1.y);
            *(float2*)(out_mem + r0 * UNITS + c) = o0;
            *(float2*)(out_mem + (r0 + 8) * UNITS + c) = o1;
        }
    }
}

// ---------------- c_wlu = (c_wu <= colmin) ----------------
__global__ void k_wlu(const float* __restrict__ out_cwu, float* __restrict__ out_cwlu) {
    __shared__ float smin[256];
    smin[threadIdx.x] = g_colmin[threadIdx.x];
    __syncthreads();
    const int total = MEMN * BATCH / 4;
    for (int i4 = blockIdx.x * 256 + threadIdx.x; i4 < total; i4 += gridDim.x * 256) {
        float4 v = *(const float4*)(out_cwu + i4 * 4);
        int c = (i4 & 63) * 4;
        float4 o;
        o.x = (v.x <= smin[c])     ? 1.f : 0.f;
        o.y = (v.y <= smin[c + 1]) ? 1.f : 0.f;
        o.z = (v.z <= smin[c + 2]) ? 1.f : 0.f;
        o.w = (v.w <= smin[c + 3]) ? 1.f : 0.f;
        *(float4*)(out_cwlu + i4 * 4) = o;
    }
}

extern "C" void kernel_launch(void* const* d_in, const int* in_sizes, int n_in,
                              void* d_out, int out_size) {
    (void)in_sizes; (void)n_in; (void)out_size;
    const float* inputs   = (const float*)d_in[0];
    const float* r_tm1    = (const float*)d_in[1];
    const float* m_tm1    = (const float*)d_in[2];
    const float* c_wu_tm1 = (const float*)d_in[3];
    const float* c_wlu_tm1= (const float*)d_in[4];
    const float* c_wr_tm1 = (const float*)d_in[5];
    const float* h_tm1    = (const float*)d_in[7];
    const float* c_tm1    = (const float*)d_in[8];
    const float* Wk       = (const float*)d_in[9];
    const float* Wr       = (const float*)d_in[10];
    const float* bias     = (const float*)d_in[11];
    const float* wgate    = (const float*)d_in[12];
    float* out = (float*)d_out;

    const int smem_cos  = (64 * PA + 128 * PB + 64) * 4;     // 103936
    const int smem_read = (64 * PB * 2) * 4;                 // 69632
    const int smem_mem  = (64 * PA + 128 * PB) * 4;          // 103424

    cudaFuncSetAttribute(k_cos,  cudaFuncAttributeMaxDynamicSharedMemorySize, smem_cos);
    cudaFuncSetAttribute(k_read, cudaFuncAttributeMaxDynamicSharedMemorySize, smem_read);
    cudaFuncSetAttribute(k_mem,  cudaFuncAttributeMaxDynamicSharedMemorySize, smem_mem);

    k_init<<<128, 256>>>(out + OFF_READ);
    k_lstm<<<dim3(8, 16), 256>>>(inputs, r_tm1, h_tm1, c_tm1, Wk, Wr, bias, out);
    k_knorm<<<32, 256>>>();
    k_cos<<<dim3(2, 512), 256, smem_cos>>>(m_tm1);
    k_soft<<<256, 256>>>(c_wr_tm1, c_wlu_tm1, c_wu_tm1, wgate, out);
    k_argmin<<<1, 256>>>();
    k_read<<<dim3(2, 64), 512, smem_read>>>(m_tm1, out + OFF_CWR, out + OFF_READ);
    k_mem<<<512, 256, smem_mem>>>(m_tm1, out + OFF_CWW, out + OFF_MEMORY);
    k_wlu<<<2048, 256>>>(out + OFF_CWU, out + OFF_CWLU);
}

// round 8
// speedup vs baseline: 1.4736x; 1.1121x over previous
#include <cuda_runtime.h>
#include <math.h>
#include <stdint.h>

#define MEMN 32768
#define BATCH 256
#define UNITS 128
#define IN_DIM 512

#define OFF_READ    0
#define OFF_MEMORY  (OFF_READ + BATCH*UNITS)
#define OFF_CWU     (OFF_MEMORY + MEMN*UNITS)
#define OFF_CWLU    (OFF_CWU + MEMN*BATCH)
#define OFF_CWR     (OFF_CWLU + MEMN*BATCH)
#define OFF_CWW     (OFF_CWR + MEMN*BATCH)
#define OFF_H       (OFF_CWW + MEMN*BATCH)
#define OFF_C       (OFF_H + BATCH*UNITS)

#define PA 132
#define PB 136

typedef unsigned long long ull;

// scratch (device globals: no allocation allowed)
__device__ float g_h[BATCH*UNITS];
__device__ float g_hT[UNITS*BATCH];          // [unit][batch]
__device__ float g_kinv[BATCH];
__device__ ull   g_colenc[BATCH];
__device__ float g_colmin[BATCH];
__device__ int   g_cnt[MEMN];

__device__ __forceinline__ unsigned ordf(float f) {
    unsigned u = __float_as_uint(f);
    return (u & 0x80000000u) ? ~u : (u | 0x80000000u);
}

__device__ __forceinline__ void mma_tf32(float* d, const unsigned* a, const unsigned* b) {
    asm volatile(
        "mma.sync.aligned.m16n8k8.row.col.f32.tf32.tf32.f32 "
        "{%0,%1,%2,%3}, {%4,%5,%6,%7}, {%8,%9}, {%0,%1,%2,%3};"
        : "+f"(d[0]), "+f"(d[1]), "+f"(d[2]), "+f"(d[3])
        : "r"(a[0]), "r"(a[1]), "r"(a[2]), "r"(a[3]), "r"(b[0]), "r"(b[1]));
}

__device__ __forceinline__ unsigned rna_tf32(float a) {
    unsigned r;
    asm("cvt.rna.tf32.f32 %0, %1;" : "=r"(r) : "f"(a));
    return r;
}
__device__ __forceinline__ void split2(float a, unsigned& hi, unsigned& lo) {
    unsigned h;
    asm("cvt.rna.tf32.f32 %0, %1;" : "=r"(h) : "f"(a));
    hi = h;
    lo = __float_as_uint(a - __uint_as_float(h));
}

// ---------------- init ----------------
__global__ void k_init(float* __restrict__ out_read) {
    int i = blockIdx.x * 256 + threadIdx.x;
    if (i < MEMN) g_cnt[i] = 0;
    if (i < BATCH*UNITS) out_read[i] = 0.f;
    if (i < BATCH) g_colenc[i] = 0xFFFFFFFFFFFFFFFFull;
}

// ---------------- LSTM cell ----------------
__global__ void k_lstm(const float* __restrict__ inputs, const float* __restrict__ r_tm1,
                       const float* __restrict__ h_tm1, const float* __restrict__ c_tm1,
                       const float* __restrict__ Wk, const float* __restrict__ Wr,
                       const float* __restrict__ bias, float* __restrict__ out) {
    __shared__ float sA[16][128];
    __shared__ float sB[128][64];
    int t = threadIdx.x;
    int utile = blockIdx.x, btile = blockIdx.y;
    int ul = t & 15, bl = t >> 4;
    float acc[4] = {0.f, 0.f, 0.f, 0.f};

    for (int kc = 0; kc < 6; kc++) {
        #pragma unroll
        for (int p = 0; p < 2; p++) {
            int i = t + p * 256;
            int row = i >> 5, c4 = (i & 31) * 4;
            int b = btile * 16 + row;
            const float* src;
            if (kc < 4)       src = inputs + b * IN_DIM + kc * 128 + c4;
            else if (kc == 4) src = r_tm1 + b * UNITS + c4;
            else              src = h_tm1 + b * UNITS + c4;
            *(float4*)&sA[row][c4] = *(const float4*)src;
        }
        #pragma unroll
        for (int p = 0; p < 8; p++) {
            int i = t + p * 256;
            int k = i >> 4, c4 = (i & 15) * 4;
            int q = c4 >> 4, jr = c4 & 15;
            int jc = utile * 16 + jr + q * 128;
            float4 v;
            if (kc < 5) v = *(const float4*)(Wk + (kc * 128 + k) * 512 + jc);
            else        v = *(const float4*)(Wr + k * 512 + jc);
            *(float4*)&sB[k][c4] = v;
        }
        __syncthreads();
        #pragma unroll 8
        for (int k = 0; k < 128; k++) {
            float a = sA[bl][k];
            acc[0] += a * sB[k][ul];
            acc[1] += a * sB[k][16 + ul];
            acc[2] += a * sB[k][32 + ul];
            acc[3] += a * sB[k][48 + ul];
        }
        __syncthreads();
    }
    int b = btile * 16 + bl, u = utile * 16 + ul;
    float zi = acc[0] + bias[u];
    float zf = acc[1] + bias[128 + u];
    float zg = acc[2] + bias[256 + u];
    float zo = acc[3] + bias[384 + u];
    float si = 1.f / (1.f + expf(-zi));
    float sf = 1.f / (1.f + expf(-zf));
    float so = 1.f / (1.f + expf(-zo));
    float cn = sf * c_tm1[b * UNITS + u] + si * tanhf(zg);
    float hn = so * tanhf(cn);
    out[OFF_H + b * UNITS + u] = hn;
    out[OFF_C + b * UNITS + u] = cn;
    g_h[b * UNITS + u] = hn;
}

// ---------------- key inverse norms + h transpose ----------------
__global__ void k_knorm() {
    int t = threadIdx.x, w = t >> 5, l = t & 31;
    int b = blockIdx.x * 8 + w;
    float s = 0.f;
    #pragma unroll
    for (int i = 0; i < 4; i++) { float v = g_h[b * UNITS + l + 32 * i]; s += v * v; }
    #pragma unroll
    for (int o = 16; o; o >>= 1) s += __shfl_xor_sync(0xffffffffu, s, o);
    if (l == 0) g_kinv[b] = rsqrtf(fmaxf(s, 1e-12f));
    #pragma unroll
    for (int p = 0; p < 4; p++) {
        int idx = blockIdx.x * 1024 + p * 256 + t;
        g_hT[(idx & 127) * BATCH + (idx >> 7)] = g_h[idx];
    }
}

// ---------------- FUSED: cos GEMM + softmax + ww/wu + col-min --------------
// grid 512 (64 m-rows each), 256 thr, 8 warps, warp tile 32m x 64n (full N=256).
// smem: sA[64][132] | sB[64][264] (k-chunk of hT) | sKinv[256] | sSS[64]
//       | sRmax[64][4] | sRsum[64][4]
__global__ void __launch_bounds__(256, 2)
k_fuse(const float* __restrict__ mptr, const float* __restrict__ wr_tm1,
       const float* __restrict__ wlu_tm1, const float* __restrict__ wu_tm1,
       const float* __restrict__ wgate, float* __restrict__ out) {
    extern __shared__ float sm[];
    float* sA    = sm;                       // 64*132 = 8448
    float* sB    = sA + 64 * 132;            // 64*264 = 16896
    float* sKinv = sB + 64 * 264;            // 256
    float* sSS   = sKinv + 256;              // 64
    float* sRmax = sSS + 64;                 // 256
    float* sRsum = sRmax + 256;              // 256

    int t = threadIdx.x;
    int lane = t & 31, wid = t >> 5;
    int qr = lane >> 2, qc = lane & 3;
    int mbase = blockIdx.x * 64;
    int wmg = wid >> 2;                      // m group 0/1
    int wng = wid & 3;                       // n group 0..3
    int wm = wmg * 32, wn = wng * 64;

    // stage A [64 rows][128 k]
    #pragma unroll
    for (int i = 0; i < 8; i++) {
        int g = t + i * 256;
        int r = g >> 5, c4 = (g & 31) << 2;
        *(float4*)&sA[r * 132 + c4] = *(const float4*)(mptr + (mbase + r) * UNITS + c4);
    }
    sKinv[t] = g_kinv[t];
    __syncthreads();
    if (t < 64) {
        float ss = 0.f;
        #pragma unroll
        for (int i = 0; i < 32; i++) {
            float4 v = *(float4*)&sA[t * 132 + i * 4];
            ss += v.x * v.x + v.y * v.y + v.z * v.z + v.w * v.w;
        }
        sSS[t] = rsqrtf(fmaxf(ss, 1e-12f));
    }

    float acc[2][8][4];
    #pragma unroll
    for (int i = 0; i < 2; i++)
        #pragma unroll
        for (int j = 0; j < 8; j++)
            #pragma unroll
            for (int q = 0; q < 4; q++) acc[i][j][q] = 0.f;

    for (int kc = 0; kc < 2; kc++) {
        // stage B chunk: hT rows [kc*64 .. +63] x all 256 batch
        #pragma unroll
        for (int i = 0; i < 16; i++) {
            int g = t + i * 256;
            int r = g >> 6, c4 = (g & 63) << 2;
            *(float4*)&sB[r * 264 + c4] = *(const float4*)(g_hT + (kc * 64 + r) * BATCH + c4);
        }
        __syncthreads();
        #pragma unroll
        for (int ks = 0; ks < 8; ks++) {
            int kbA = kc * 64 + ks * 8;
            int kbB = ks * 8;
            unsigned ah[2][4], al[2][4], bb[8][2];
            #pragma unroll
            for (int mt = 0; mt < 2; mt++) {
                int rb = wm + mt * 16;
                split2(sA[(rb + qr) * 132 + kbA + qc],         ah[mt][0], al[mt][0]);
                split2(sA[(rb + 8 + qr) * 132 + kbA + qc],     ah[mt][1], al[mt][1]);
                split2(sA[(rb + qr) * 132 + kbA + 4 + qc],     ah[mt][2], al[mt][2]);
                split2(sA[(rb + 8 + qr) * 132 + kbA + 4 + qc], ah[mt][3], al[mt][3]);
            }
            #pragma unroll
            for (int nt = 0; nt < 8; nt++) {
                int cb = wn + nt * 8;
                bb[nt][0] = rna_tf32(sB[(kbB + qc) * 264 + cb + qr]);
                bb[nt][1] = rna_tf32(sB[(kbB + 4 + qc) * 264 + cb + qr]);
            }
            #pragma unroll
            for (int mt = 0; mt < 2; mt++)
                #pragma unroll
                for (int nt = 0; nt < 8; nt++) {
                    mma_tf32(acc[mt][nt], ah[mt], bb[nt]);
                    mma_tf32(acc[mt][nt], al[mt], bb[nt]);
                }
        }
        __syncthreads();
    }

    // ---- scale to cosine: acc *= minv[row] * kinv[col] ----
    #pragma unroll
    for (int mt = 0; mt < 2; mt++) {
        float s0 = sSS[wm + mt * 16 + qr];
        float s1 = sSS[wm + mt * 16 + qr + 8];
        #pragma unroll
        for (int nt = 0; nt < 8; nt++) {
            float k0 = sKinv[wn + nt * 8 + 2 * qc];
            float k1 = sKinv[wn + nt * 8 + 2 * qc + 1];
            acc[mt][nt][0] *= s0 * k0;
            acc[mt][nt][1] *= s0 * k1;
            acc[mt][nt][2] *= s1 * k0;
            acc[mt][nt][3] *= s1 * k1;
        }
    }

    // ---- row max (per row-slot: mt, h) ----
    float rmax[2][2];
    #pragma unroll
    for (int mt = 0; mt < 2; mt++)
        #pragma unroll
        for (int h = 0; h < 2; h++) {
            float m = -1e30f;
            #pragma unroll
            for (int nt = 0; nt < 8; nt++) {
                m = fmaxf(m, acc[mt][nt][2 * h]);
                m = fmaxf(m, acc[mt][nt][2 * h + 1]);
            }
            m = fmaxf(m, __shfl_xor_sync(0xffffffffu, m, 1));
            m = fmaxf(m, __shfl_xor_sync(0xffffffffu, m, 2));
            rmax[mt][h] = m;
        }
    if (qc == 0) {
        #pragma unroll
        for (int mt = 0; mt < 2; mt++)
            #pragma unroll
            for (int h = 0; h < 2; h++)
                sRmax[(wm + mt * 16 + qr + h * 8) * 4 + wng] = rmax[mt][h];
    }
    __syncthreads();
    #pragma unroll
    for (int mt = 0; mt < 2; mt++)
        #pragma unroll
        for (int h = 0; h < 2; h++) {
            int rl = (wm + mt * 16 + qr + h * 8) * 4;
            rmax[mt][h] = fmaxf(fmaxf(sRmax[rl], sRmax[rl + 1]),
                                fmaxf(sRmax[rl + 2], sRmax[rl + 3]));
        }

    // ---- exp in place + row sum ----
    float rsum[2][2];
    #pragma unroll
    for (int mt = 0; mt < 2; mt++)
        #pragma unroll
        for (int h = 0; h < 2; h++) {
            float s = 0.f;
            float m = rmax[mt][h];
            #pragma unroll
            for (int nt = 0; nt < 8; nt++) {
                float e0 = __expf(acc[mt][nt][2 * h] - m);
                float e1 = __expf(acc[mt][nt][2 * h + 1] - m);
                acc[mt][nt][2 * h] = e0;
                acc[mt][nt][2 * h + 1] = e1;
                s += e0 + e1;
            }
            s += __shfl_xor_sync(0xffffffffu, s, 1);
            s += __shfl_xor_sync(0xffffffffu, s, 2);
            rsum[mt][h] = s;
        }
    if (qc == 0) {
        #pragma unroll
        for (int mt = 0; mt < 2; mt++)
            #pragma unroll
            for (int h = 0; h < 2; h++)
                sRsum[(wm + mt * 16 + qr + h * 8) * 4 + wng] = rsum[mt][h];
    }
    __syncthreads();
    float rinv[2][2];
    #pragma unroll
    for (int mt = 0; mt < 2; mt++)
        #pragma unroll
        for (int h = 0; h < 2; h++) {
            int rl = (wm + mt * 16 + qr + h * 8) * 4;
            rinv[mt][h] = 1.f / (sRsum[rl] + sRsum[rl + 1] + sRsum[rl + 2] + sRsum[rl + 3]);
        }

    // ---- outputs + per-column min ----
    float wg = 1.f / (1.f + __expf(-wgate[0]));
    float omw = 1.f - wg;
    ull emin[8][2];
    #pragma unroll
    for (int nt = 0; nt < 8; nt++) { emin[nt][0] = ~0ull; emin[nt][1] = ~0ull; }

    #pragma unroll
    for (int mt = 0; mt < 2; mt++) {
        #pragma unroll
        for (int h = 0; h < 2; h++) {
            int rowg = mbase + wm + mt * 16 + qr + h * 8;
            float inv = rinv[mt][h];
            ull lw = (ull)(0xFFFFFFFFu - (unsigned)rowg);
            #pragma unroll
            for (int nt = 0; nt < 8; nt++) {
                int col = wn + nt * 8 + 2 * qc;
                int idx = rowg * BATCH + col;
                float2 wrp = make_float2(acc[mt][nt][2 * h] * inv, acc[mt][nt][2 * h + 1] * inv);
                float2 wrt = *(const float2*)(wr_tm1 + idx);
                float2 wlt = *(const float2*)(wlu_tm1 + idx);
                float2 wut = *(const float2*)(wu_tm1 + idx);
                float2 ww = make_float2(wg * wrt.x + omw + wlt.x, wg * wrt.y + omw + wlt.y);
                float2 wu = make_float2(0.95f * wut.x + wrp.x + ww.x, 0.95f * wut.y + wrp.y + ww.y);
                *(float2*)&out[OFF_CWR + idx] = wrp;
                *(float2*)&out[OFF_CWW + idx] = ww;
                *(float2*)&out[OFF_CWU + idx] = wu;
                ull e0 = ((ull)ordf(wu.x) << 32) | lw;
                ull e1 = ((ull)ordf(wu.y) << 32) | lw;
                emin[nt][0] = (e0 < emin[nt][0]) ? e0 : emin[nt][0];
                emin[nt][1] = (e1 < emin[nt][1]) ? e1 : emin[nt][1];
            }
        }
    }
    // reduce over qr lanes (bits 2..4), then atomic per column
    #pragma unroll
    for (int nt = 0; nt < 8; nt++)
        #pragma unroll
        for (int e = 0; e < 2; e++) {
            ull v = emin[nt][e];
            ull o = __shfl_xor_sync(0xffffffffu, v, 4);  v = (o < v) ? o : v;
            o = __shfl_xor_sync(0xffffffffu, v, 8);      v = (o < v) ? o : v;
            o = __shfl_xor_sync(0xffffffffu, v, 16);     v = (o < v) ? o : v;
            emin[nt][e] = v;
        }
    if (qr == 0) {
        #pragma unroll
        for (int nt = 0; nt < 8; nt++) {
            int col = wn + nt * 8 + 2 * qc;
            atomicMin(&g_colenc[col], emin[nt][0]);
            atomicMin(&g_colenc[col + 1], emin[nt][1]);
        }
    }
}

// ---------------- finalize argmin ---------------- 1 x 256
__global__ void k_fin() {
    int c = threadIdx.x;
    ull e = g_colenc[c];
    unsigned hi = (unsigned)(e >> 32);
    unsigned bits = (hi & 0x80000000u) ? (hi & 0x7FFFFFFFu) : ~hi;
    g_colmin[c] = __uint_as_float(bits);
    int idx = (int)(0xFFFFFFFFu - (unsigned)(e & 0xFFFFFFFFull));
    atomicAdd(&g_cnt[idx], 1);
}

// ---------------- read = c_wr.T @ m_tm1, 2-MMA split, split-K --------------
// grid (4 btiles of 64, 64 kchunks of 512), 256 thr. CTA 64b x 128u.
__global__ void __launch_bounds__(256) k_read(const float* __restrict__ mptr,
                                              const float* __restrict__ cwr,
                                              float* __restrict__ out_read) {
    extern __shared__ float sm[];
    float* sW = sm;                  // [64][72]  wr chunk [k][b64]
    float* sM = sm + 64 * 72;        // [64][136] m chunk [k][u]

    int t = threadIdx.x;
    int lane = t & 31, wid = t >> 5;
    int qr = lane >> 2, qc = lane & 3;
    int bbase = blockIdx.x * 64;
    int kchunk = blockIdx.y;
    int wm = (wid >> 2) * 32, wn = (wid & 3) * 32;

    float acc[2][4][4];
    #pragma unroll
    for (int i = 0; i < 2; i++)
        #pragma unroll
        for (int j = 0; j < 4; j++)
            #pragma unroll
            for (int q = 0; q < 4; q++) acc[i][j][q] = 0.f;

    for (int it = 0; it < 8; it++) {
        int kb0 = kchunk * 512 + it * 64;
        #pragma unroll
        for (int i = 0; i < 4; i++) {
            int g = t + i * 256;
            int r = g >> 4, c4 = (g & 15) << 2;
            *(float4*)&sW[r * 72 + c4] = *(const float4*)(cwr + (kb0 + r) * BATCH + bbase + c4);
        }
        #pragma unroll
        for (int i = 0; i < 8; i++) {
            int g = t + i * 256;
            int r = g >> 5, c4 = (g & 31) << 2;
            *(float4*)&sM[r * 136 + c4] = *(const float4*)(mptr + (kb0 + r) * UNITS + c4);
        }
        __syncthreads();
        #pragma unroll
        for (int ks = 0; ks < 8; ks++) {
            int kb = ks * 8;
            unsigned ah[2][4], al[2][4], bb[4][2];
            #pragma unroll
            for (int mt = 0; mt < 2; mt++) {
                int rb = wm + mt * 16;
                split2(sW[(kb + qc) * 72 + rb + qr],         ah[mt][0], al[mt][0]);
                split2(sW[(kb + qc) * 72 + rb + 8 + qr],     ah[mt][1], al[mt][1]);
                split2(sW[(kb + 4 + qc) * 72 + rb + qr],     ah[mt][2], al[mt][2]);
                split2(sW[(kb + 4 + qc) * 72 + rb + 8 + qr], ah[mt][3], al[mt][3]);
            }
            #pragma unroll
            for (int nt = 0; nt < 4; nt++) {
                int cb = wn + nt * 8;
                bb[nt][0] = rna_tf32(sM[(kb + qc) * 136 + cb + qr]);
                bb[nt][1] = rna_tf32(sM[(kb + 4 + qc) * 136 + cb + qr]);
            }
            #pragma unroll
            for (int mt = 0; mt < 2; mt++)
                #pragma unroll
                for (int nt = 0; nt < 4; nt++) {
                    mma_tf32(acc[mt][nt], ah[mt], bb[nt]);
                    mma_tf32(acc[mt][nt], al[mt], bb[nt]);
                }
        }
        __syncthreads();
    }
    #pragma unroll
    for (int mt = 0; mt < 2; mt++) {
        int r0 = bbase + wm + mt * 16 + qr;
        #pragma unroll
        for (int nt = 0; nt < 4; nt++) {
            int c = wn + nt * 8 + 2 * qc;
            atomicAdd(&out_read[r0 * UNITS + c],           acc[mt][nt][0]);
            atomicAdd(&out_read[r0 * UNITS + c + 1],       acc[mt][nt][1]);
            atomicAdd(&out_read[(r0 + 8) * UNITS + c],     acc[mt][nt][2]);
            atomicAdd(&out_read[(r0 + 8) * UNITS + c + 1], acc[mt][nt][3]);
        }
    }
}

// ---------------- memory = c_ww @ h + (256 - cnt[m]) * m_tm1 ---------------
// grid 512 mtiles, 256 thr. CTA 64m x 128u, K=256 in 2 halves, 2 CTAs/SM.
__global__ void __launch_bounds__(256) k_mem(const float* __restrict__ mptr,
                                             const float* __restrict__ cww,
                                             float* __restrict__ out_mem) {
    extern __shared__ float sm[];
    float* sA = sm;                  // [64][PA]   cww half [row][k]
    float* sB = sm + 64 * PA;        // [128][PB]  h half [k=b][u]

    int t = threadIdx.x;
    int lane = t & 31, wid = t >> 5;
    int qr = lane >> 2, qc = lane & 3;
    int mbase = blockIdx.x * 64;
    int wm = (wid >> 2) * 32, wn = (wid & 3) * 32;

    float acc[2][4][4];
    #pragma unroll
    for (int i = 0; i < 2; i++)
        #pragma unroll
        for (int j = 0; j < 4; j++)
            #pragma unroll
            for (int q = 0; q < 4; q++) acc[i][j][q] = 0.f;

    for (int kc = 0; kc < 2; kc++) {
        #pragma unroll
        for (int i = 0; i < 8; i++) {
            int g = t + i * 256;
            int r = g >> 5, c4 = (g & 31) << 2;
            *(float4*)&sA[r * PA + c4] = *(const float4*)(cww + (mbase + r) * BATCH + kc * 128 + c4);
        }
        #pragma unroll
        for (int i = 0; i < 16; i++) {
            int g = t + i * 256;
            int r = g >> 5, c4 = (g & 31) << 2;
            *(float4*)&sB[r * PB + c4] = *(const float4*)(g_h + (kc * 128 + r) * UNITS + c4);
        }
        __syncthreads();
        #pragma unroll
        for (int ks = 0; ks < 16; ks++) {
            int kb = ks * 8;
            unsigned ah[2][4], al[2][4], bb[4][2];
            #pragma unroll
            for (int mt = 0; mt < 2; mt++) {
                int rb = wm + mt * 16;
                split2(sA[(rb + qr) * PA + kb + qc],         ah[mt][0], al[mt][0]);
                split2(sA[(rb + 8 + qr) * PA + kb + qc],     ah[mt][1], al[mt][1]);
                split2(sA[(rb + qr) * PA + kb + 4 + qc],     ah[mt][2], al[mt][2]);
                split2(sA[(rb + 8 + qr) * PA + kb + 4 + qc], ah[mt][3], al[mt][3]);
            }
            #pragma unroll
            for (int nt = 0; nt < 4; nt++) {
                int cb = wn + nt * 8;
                bb[nt][0] = rna_tf32(sB[(kb + qc) * PB + cb + qr]);
                bb[nt][1] = rna_tf32(sB[(kb + 4 + qc) * PB + cb + qr]);
            }
            #pragma unroll
            for (int mt = 0; mt < 2; mt++)
                #pragma unroll
                for (int nt = 0; nt < 4; nt++) {
                    mma_tf32(acc[mt][nt], ah[mt], bb[nt]);
                    mma_tf32(acc[mt][nt], al[mt], bb[nt]);
                }
        }
        __syncthreads();
    }

    #pragma unroll
    for (int mt = 0; mt < 2; mt++) {
        int r0 = mbase + wm + mt * 16 + qr;
        float f0 = (float)(BATCH - g_cnt[r0]);
        float f1 = (float)(BATCH - g_cnt[r0 + 8]);
        #pragma unroll
        for (int nt = 0; nt < 4; nt++) {
            int c = wn + nt * 8 + 2 * qc;
            float2 m0 = *(const float2*)(mptr + r0 * UNITS + c);
            float2 m1 = *(const float2*)(mptr + (r0 + 8) * UNITS + c);
            float2 o0 = make_float2(acc[mt][nt][0] + f0 * m0.x, acc[mt][nt][1] + f0 * m0.y);
            float2 o1 = make_float2(acc[mt][nt][2] + f1 * m1.x, acc[mt][nt][3] + f1 * m1.y);
            *(float2*)(out_mem + r0 * UNITS + c) = o0;
            *(float2*)(out_mem + (r0 + 8) * UNITS + c) = o1;
        }
    }
}

// ---------------- c_wlu = (c_wu <= colmin) ----------------
__global__ void k_wlu(const float* __restrict__ out_cwu, float* __restrict__ out_cwlu) {
    __shared__ float smin[256];
    smin[threadIdx.x] = g_colmin[threadIdx.x];
    __syncthreads();
    const int total = MEMN * BATCH / 4;
    for (int i4 = blockIdx.x * 256 + threadIdx.x; i4 < total; i4 += gridDim.x * 256) {
        float4 v = *(const float4*)(out_cwu + i4 * 4);
        int c = (i4 & 63) * 4;
        float4 o;
        o.x = (v.x <= smin[c])     ? 1.f : 0.f;
        o.y = (v.y <= smin[c + 1]) ? 1.f : 0.f;
        o.z = (v.z <= smin[c + 2]) ? 1.f : 0.f;
        o.w = (v.w <= smin[c + 3]) ? 1.f : 0.f;
        *(float4*)(out_cwlu + i4 * 4) = o;
    }
}

extern "C" void kernel_launch(void* const* d_in, const int* in_sizes, int n_in,
                              void* d_out, int out_size) {
    (void)in_sizes; (void)n_in; (void)out_size;
    const float* inputs   = (const float*)d_in[0];
    const float* r_tm1    = (const float*)d_in[1];
    const float* m_tm1    = (const float*)d_in[2];
    const float* c_wu_tm1 = (const float*)d_in[3];
    const float* c_wlu_tm1= (const float*)d_in[4];
    const float* c_wr_tm1 = (const float*)d_in[5];
    const float* h_tm1    = (const float*)d_in[7];
    const float* c_tm1    = (const float*)d_in[8];
    const float* Wk       = (const float*)d_in[9];
    const float* Wr       = (const float*)d_in[10];
    const float* bias     = (const float*)d_in[11];
    const float* wgate    = (const float*)d_in[12];
    float* out = (float*)d_out;

    const int smem_fuse = (64 * 132 + 64 * 264 + 256 + 64 + 256 + 256) * 4;  // 104704
    const int smem_read = (64 * 72 + 64 * 136) * 4;                          // 53248
    const int smem_mem  = (64 * PA + 128 * PB) * 4;                          // 103424

    cudaFuncSetAttribute(k_fuse, cudaFuncAttributeMaxDynamicSharedMemorySize, smem_fuse);
    cudaFuncSetAttribute(k_read, cudaFuncAttributeMaxDynamicSharedMemorySize, smem_read);
    cudaFuncSetAttribute(k_mem,  cudaFuncAttributeMaxDynamicSharedMemorySize, smem_mem);

    k_init<<<128, 256>>>(out + OFF_READ);
    k_lstm<<<dim3(8, 16), 256>>>(inputs, r_tm1, h_tm1, c_tm1, Wk, Wr, bias, out);
    k_knorm<<<32, 256>>>();
    k_fuse<<<512, 256, smem_fuse>>>(m_tm1, c_wr_tm1, c_wlu_tm1, c_wu_tm1, wgate, out);
    k_fin<<<1, 256>>>();
    k_read<<<dim3(4, 64), 256, smem_read>>>(m_tm1, out + OFF_CWR, out + OFF_READ);
    k_mem<<<512, 256, smem_mem>>>(m_tm1, out + OFF_CWW, out + OFF_MEMORY);
    k_wlu<<<2048, 256>>>(out + OFF_CWU, out + OFF_CWLU);
}